// round 10
// baseline (speedup 1.0000x reference)
#include <cuda_runtime.h>
#include <math.h>
#include <stdint.h>

#define B_      256
#define L_      16
#define H_      256
#define V_      5000
#define P_      4
#define NPG_    150
#define DEG_    4
#define EPG_    (NPG_*DEG_)
#define STEPS_  4
#define OUT_    2000
#define N_      (B_*NPG_)
#define E_      (N_*DEG_)
#define BL_     (B_*L_)
#define LDLOG_  5008

// ---------------- scratch arena ----------------
static constexpr size_t SZ_C    = (size_t)(V_+1)*H_;
static constexpr size_t SZ_XW   = (size_t)BL_*H_;
static constexpr size_t SZ_LOG  = (size_t)BL_*LDLOG_;
static constexpr size_t SZ_VT   = (size_t)BL_*H_;
static constexpr size_t SZ_XG   = (size_t)BL_*4*H_;
static constexpr size_t SZ_H    = (size_t)B_*H_;
static constexpr size_t SZ_HINS = (size_t)B_*STEPS_*H_;
static constexpr size_t SZ_TR   = (size_t)N_*3*H_;
static constexpr size_t SZ_ET   = (size_t)E_*H_;

static constexpr size_t OFF_C    = 0;
static constexpr size_t OFF_XW   = OFF_C    + SZ_C;
static constexpr size_t OFF_LOG  = OFF_XW   + SZ_XW;
static constexpr size_t OFF_VT   = OFF_LOG  + SZ_LOG;
static constexpr size_t OFF_XG   = OFF_VT   + SZ_VT;
static constexpr size_t OFF_H    = OFF_XG   + SZ_XG;
static constexpr size_t OFF_CS   = OFF_H    + SZ_H;
static constexpr size_t OFF_H2   = OFF_CS   + SZ_H;
static constexpr size_t OFF_R    = OFF_H2   + SZ_H;
static constexpr size_t OFF_PS   = OFF_R    + SZ_HINS;
static constexpr size_t OFF_TR   = OFF_PS   + (size_t)B_*STEPS_*P_;
static constexpr size_t OFF_ET   = OFF_TR   + SZ_TR;
static constexpr size_t OFF_NS4  = OFF_ET   + SZ_ET;
static constexpr size_t OFF_ES4  = OFF_NS4  + (size_t)N_*4;
static constexpr size_t OFF_DIST = OFF_ES4  + (size_t)E_*4;
static constexpr size_t OFF_QA   = OFF_DIST + N_;
static constexpr size_t OFF_WNT  = OFF_QA   + (size_t)B_*2*H_;
static constexpr size_t OFF_VOCT = OFF_WNT  + (size_t)H_*H_;
static constexpr size_t OFF_WIHT = OFF_VOCT + (size_t)H_*LDLOG_;
static constexpr size_t OFF_WHHT = OFF_WIHT + (size_t)H_*H_;
static constexpr size_t TOTAL_SCRATCH = OFF_WHHT + (size_t)H_*H_;

__device__ __align__(16) float g_scratch[TOTAL_SCRATCH];

// ---------------- helpers ----------------
__device__ __forceinline__ float warp_sum(float v) {
    #pragma unroll
    for (int o = 16; o > 0; o >>= 1) v += __shfl_down_sync(0xffffffffu, v, o);
    return v;
}
__device__ __forceinline__ float sigmoidf_(float x) { return 1.f / (1.f + expf(-x)); }
__device__ __forceinline__ uint32_t f2tf32(float x) {
    uint32_t u;
    asm("cvt.rna.tf32.f32 %0, %1;" : "=r"(u) : "f"(x));
    return u;
}
__device__ __forceinline__ uint32_t smem_u32(const void* p) {
    uint32_t a;
    asm("{ .reg .u64 t; cvta.to.shared.u64 t, %1; cvt.u32.u64 %0, t; }" : "=r"(a) : "l"(p));
    return a;
}
__device__ __forceinline__ void cp_async16(void* sdst, const void* gsrc, bool pred) {
    uint32_t d = smem_u32(sdst);
    int sz = pred ? 16 : 0;
    asm volatile("cp.async.cg.shared.global [%0], [%1], 16, %2;"
                 :: "r"(d), "l"(gsrc), "r"(sz));
}
__device__ __forceinline__ void cp_commit() {
    asm volatile("cp.async.commit_group;" ::: "memory");
}
template<int N>
__device__ __forceinline__ void cp_wait() {
    asm volatile("cp.async.wait_group %0;" :: "n"(N) : "memory");
}
__device__ __forceinline__ void mma_tf32(float* d, const uint32_t* a, const uint32_t* b) {
    asm volatile(
        "mma.sync.aligned.m16n8k8.row.col.f32.tf32.tf32.f32 "
        "{%0,%1,%2,%3}, {%4,%5,%6,%7}, {%8,%9}, {%0,%1,%2,%3};"
        : "+f"(d[0]), "+f"(d[1]), "+f"(d[2]), "+f"(d[3])
        : "r"(a[0]), "r"(a[1]), "r"(a[2]), "r"(a[3]), "r"(b[0]), "r"(b[1]));
}

// ---------------- tf32 GEMM: CTA 128x128x32, 256 thr, warp 32x64 (4x2) ----------------
// cvt.rna.tf32 applied at fragment-load time (round-to-nearest: required for accuracy).
#define GB_M 128
#define GB_N 128
#define GB_K 32
#define GTS  36
#define GABUF (GB_M*GTS)
#define GBBUF (GB_N*GTS)
#define G_SMEM_BYTES ((2*GABUF + 2*GBBUF)*4)

__global__ void __launch_bounds__(256, 2)
mma_gemm_k(const float* __restrict__ A, int lda,
           const float* __restrict__ Bm, int ldb,
           float* __restrict__ C, int ldc,
           int M, int N, int K, const float* __restrict__ bias, int splitk)
{
    extern __shared__ float smf[];
    float* As = smf;
    float* Bs = smf + 2*GABUF;
    const int tid  = threadIdx.x;
    const int wid  = tid >> 5, lane = tid & 31;
    const int g    = lane >> 2, t4 = lane & 3;
    const int wm   = wid & 3, wn = wid >> 2;
    const int bm   = blockIdx.y * GB_M;
    const int bn   = blockIdx.x * GB_N;

    int kbeg = 0, kend = K;
    if (splitk > 1) {
        int kslen = (((K + splitk - 1) / splitk) + 3) & ~3;
        kbeg  = blockIdx.z * kslen;
        kend  = min(K, kbeg + kslen);
    }

    float acc[2][8][4];
    #pragma unroll
    for (int i = 0; i < 2; i++)
        #pragma unroll
        for (int j = 0; j < 8; j++)
            #pragma unroll
            for (int q = 0; q < 4; q++) acc[i][j][q] = 0.f;

    const int lrow = tid >> 3, lc4 = (tid & 7) << 2;

    auto issue_chunk = [&](int c) {
        int k0 = kbeg + c * GB_K;
        int buf = c & 1;
        #pragma unroll
        for (int i = 0; i < 4; i++) {
            int row = lrow + i*32;
            int gm = bm + row, gk = k0 + lc4;
            cp_async16(As + buf*GABUF + row*GTS + lc4,
                       A + (size_t)gm*lda + gk, (gm < M) && (gk < kend));
        }
        #pragma unroll
        for (int i = 0; i < 4; i++) {
            int row = lrow + i*32;
            int gn = bn + row, gk = k0 + lc4;
            cp_async16(Bs + buf*GBBUF + row*GTS + lc4,
                       Bm + (size_t)gn*ldb + gk, (gn < N) && (gk < kend));
        }
        cp_commit();
    };

    const int nch = (kend - kbeg + GB_K - 1) / GB_K;
    issue_chunk(0);

    for (int c = 0; c < nch; c++) {
        if (c + 1 < nch) { issue_chunk(c + 1); cp_wait<1>(); }
        else             { cp_wait<0>(); }
        __syncthreads();

        const float* Ab = As + (c & 1)*GABUF;
        const float* Bb = Bs + (c & 1)*GBBUF;
        #pragma unroll
        for (int ks = 0; ks < 4; ks++) {
            uint32_t af[2][4], bf[8][2];
            #pragma unroll
            for (int mt = 0; mt < 2; mt++) {
                int r0 = (wm*32 + mt*16 + g)*GTS + ks*8 + t4;
                af[mt][0] = f2tf32(Ab[r0]);
                af[mt][1] = f2tf32(Ab[r0 + 8*GTS]);
                af[mt][2] = f2tf32(Ab[r0 + 4]);
                af[mt][3] = f2tf32(Ab[r0 + 8*GTS + 4]);
            }
            #pragma unroll
            for (int nt = 0; nt < 8; nt++) {
                int rb = (wn*64 + nt*8 + g)*GTS + ks*8 + t4;
                bf[nt][0] = f2tf32(Bb[rb]);
                bf[nt][1] = f2tf32(Bb[rb + 4]);
            }
            #pragma unroll
            for (int mt = 0; mt < 2; mt++)
                #pragma unroll
                for (int nt = 0; nt < 8; nt++)
                    mma_tf32(acc[mt][nt], af[mt], bf[nt]);
        }
        __syncthreads();
    }

    const bool addb = (bias != nullptr) && (blockIdx.z == 0);
    #pragma unroll
    for (int mt = 0; mt < 2; mt++) {
        int row0 = bm + wm*32 + mt*16 + g;
        #pragma unroll
        for (int nt = 0; nt < 8; nt++) {
            int col0 = bn + wn*64 + nt*8 + t4*2;
            float b0v = 0.f, b1v = 0.f;
            if (addb) {
                if (col0     < N) b0v = bias[col0];
                if (col0 + 1 < N) b1v = bias[col0+1];
            }
            if (splitk > 1) {
                if (row0 < M) {
                    if (col0     < N) atomicAdd(&C[(size_t)row0*ldc + col0    ], acc[mt][nt][0] + b0v);
                    if (col0 + 1 < N) atomicAdd(&C[(size_t)row0*ldc + col0 + 1], acc[mt][nt][1] + b1v);
                }
                if (row0 + 8 < M) {
                    if (col0     < N) atomicAdd(&C[(size_t)(row0+8)*ldc + col0    ], acc[mt][nt][2] + b0v);
                    if (col0 + 1 < N) atomicAdd(&C[(size_t)(row0+8)*ldc + col0 + 1], acc[mt][nt][3] + b1v);
                }
            } else {
                if (row0 < M) {
                    if (col0     < N) C[(size_t)row0*ldc + col0    ] = acc[mt][nt][0] + b0v;
                    if (col0 + 1 < N) C[(size_t)row0*ldc + col0 + 1] = acc[mt][nt][1] + b1v;
                }
                if (row0 + 8 < M) {
                    if (col0     < N) C[(size_t)(row0+8)*ldc + col0    ] = acc[mt][nt][2] + b0v;
                    if (col0 + 1 < N) C[(size_t)(row0+8)*ldc + col0 + 1] = acc[mt][nt][3] + b1v;
                }
            }
        }
    }
}

// ---------------- fused LSTM step ----------------
__global__ void __launch_bounds__(256)
lstm_step_k(const float* __restrict__ hin,
            float* __restrict__ hout,
            float* __restrict__ cst,
            const float* __restrict__ Xg,
            const float* __restrict__ Whh,
            const float* __restrict__ bhh,
            const int* __restrict__ lengths, int t)
{
    __shared__ float As[8][64];
    __shared__ float Bs[8][64];
    __shared__ float Cs[64][65];
    const int tid = threadIdx.x;
    const int hh0 = blockIdx.x * 16;
    const int bm  = blockIdx.y * 64;
    const int tx = tid & 15, ty = tid >> 4;

    float acc[4][4];
    #pragma unroll
    for (int i = 0; i < 4; i++)
        #pragma unroll
        for (int j = 0; j < 4; j++) acc[i][j] = 0.f;

    for (int k0 = 0; k0 < H_; k0 += 8) {
        if (tid < 128) {
            int m = tid >> 1, kq = (tid & 1)*4;
            float4 v = *reinterpret_cast<const float4*>(hin + (size_t)(bm+m)*H_ + k0 + kq);
            As[kq+0][m]=v.x; As[kq+1][m]=v.y; As[kq+2][m]=v.z; As[kq+3][m]=v.w;
        } else {
            int it = tid - 128;
            int j = it >> 1, kq = (it & 1)*4;
            int gn = (j >> 4)*H_ + hh0 + (j & 15);
            float4 v = *reinterpret_cast<const float4*>(Whh + (size_t)gn*H_ + k0 + kq);
            Bs[kq+0][j]=v.x; Bs[kq+1][j]=v.y; Bs[kq+2][j]=v.z; Bs[kq+3][j]=v.w;
        }
        __syncthreads();
        #pragma unroll
        for (int k = 0; k < 8; k++) {
            float ar[4], br[4];
            #pragma unroll
            for (int i = 0; i < 4; i++) ar[i] = As[k][ty*4+i];
            #pragma unroll
            for (int j = 0; j < 4; j++) br[j] = Bs[k][tx*4+j];
            #pragma unroll
            for (int i = 0; i < 4; i++)
                #pragma unroll
                for (int j = 0; j < 4; j++)
                    acc[i][j] = fmaf(ar[i], br[j], acc[i][j]);
        }
        __syncthreads();
    }
    #pragma unroll
    for (int i = 0; i < 4; i++)
        #pragma unroll
        for (int j = 0; j < 4; j++)
            Cs[ty*4+i][tx*4+j] = acc[i][j];
    __syncthreads();

    #pragma unroll
    for (int i = 0; i < 4; i++) {
        int cell = i*256 + tid;
        int b_l = cell >> 4, hh_l = cell & 15;
        int b = bm + b_l, hh = hh0 + hh_l;
        const float* xrow = Xg + (size_t)(b*L_ + t)*(4*H_);
        float gi = Cs[b_l][0*16+hh_l] + xrow[hh]        + bhh[hh];
        float gf = Cs[b_l][1*16+hh_l] + xrow[H_+hh]     + bhh[H_+hh];
        float gc = Cs[b_l][2*16+hh_l] + xrow[2*H_+hh]   + bhh[2*H_+hh];
        float go = Cs[b_l][3*16+hh_l] + xrow[3*H_+hh]   + bhh[3*H_+hh];
        size_t idx = (size_t)b*H_ + hh;
        float hold = hin[idx];
        if (t < lengths[b]) {
            float cn = sigmoidf_(gf)*cst[idx] + sigmoidf_(gi)*tanhf(gc);
            cst[idx] = cn;
            hout[idx] = sigmoidf_(go)*tanhf(cn);
        } else {
            hout[idx] = hold;
        }
    }
}

// ---------------- fused decoder RNN + attention ----------------
__global__ void __launch_bounds__(256)
dec_attn_k(const float* __restrict__ Q,
           const float* __restrict__ WihT,
           const float* __restrict__ WhhT,
           const float* __restrict__ bih, const float* __restrict__ bhh,
           const float* __restrict__ Vt,
           const int* __restrict__ lengths,
           float* __restrict__ R)
{
    int b = blockIdx.x, tid = threadIdx.x;
    __shared__ float shh[H_], sQ[H_], sh[H_];
    __shared__ float sV[L_][H_];
    __shared__ float sHins[STEPS_][H_];
    __shared__ float satt[STEPS_][L_];

    shh[tid] = Q[(size_t)b*H_ + tid];
    for (int i = tid; i < L_*H_; i += 256) sV[i>>8][i&255] = Vt[(size_t)b*L_*H_ + i];
    __syncthreads();

    float acc = bih[tid];
    #pragma unroll 8
    for (int k = 0; k < H_; k++) acc = fmaf(shh[k], WihT[(size_t)k*H_ + tid], acc);
    sQ[tid] = acc;
    sh[tid] = 0.f;
    __syncthreads();

    for (int s = 0; s < STEPS_; s++) {
        float v = sQ[tid] + bhh[tid];
        #pragma unroll 8
        for (int k = 0; k < H_; k++) v = fmaf(sh[k], WhhT[(size_t)k*H_ + tid], v);
        v = fmaxf(v, 0.f);
        __syncthreads();
        sh[tid] = v;
        sHins[s][tid] = v;
        __syncthreads();
    }

    int warp = tid >> 5, lane = tid & 31;
    for (int pid = warp; pid < STEPS_*L_; pid += 8) {
        int s = pid >> 4, l = pid & 15;
        float a = 0.f;
        #pragma unroll
        for (int q = 0; q < H_/32; q++) a = fmaf(sHins[s][lane+32*q], sV[l][lane+32*q], a);
        a = warp_sum(a);
        if (lane == 0) satt[s][l] = a;
    }
    __syncthreads();
    if (tid < STEPS_) {
        int len = lengths[b];
        float m = -3.4e38f;
        for (int l = 0; l < len; l++) m = fmaxf(m, satt[tid][l]);
        float s = 0.f;
        for (int l = 0; l < len; l++) { float e = expf(satt[tid][l]-m); satt[tid][l]=e; s+=e; }
        float inv = 1.f/s;
        for (int l = 0; l < L_; l++) satt[tid][l] = (l < len) ? satt[tid][l]*inv : 0.f;
    }
    __syncthreads();
    for (int s = 0; s < STEPS_; s++) {
        float a2 = 0.f;
        #pragma unroll
        for (int l = 0; l < L_; l++) a2 = fmaf(satt[s][l], sV[l][tid], a2);
        R[((size_t)b*STEPS_ + s)*H_ + tid] = a2;
    }
}

// ---------------- small kernels ----------------
__global__ void build_c_k(const float* __restrict__ vocab, const float* __restrict__ de,
                          float* __restrict__ Cc) {
    int i = blockIdx.x*256 + threadIdx.x;
    if (i < (V_+1)*H_) Cc[i] = (i < V_*H_) ? vocab[i] : de[i - (size_t)V_*H_];
}

__global__ void transpose_wn_k(const float* __restrict__ W, float* __restrict__ WT) {
    __shared__ float t[32][33];
    int rb = blockIdx.y*32, cb = blockIdx.x*32;
    int x = threadIdx.x, y = threadIdx.y;
    for (int j = y; j < 32; j += 8) t[j][x] = W[(size_t)(rb+j)*H_ + cb + x];
    __syncthreads();
    for (int j = y; j < 32; j += 8) WT[(size_t)(cb+j)*H_ + rb + x] = t[x][j];
}

__global__ void vocab_t_k(const float* __restrict__ vocab, float* __restrict__ vt) {
    __shared__ float t[32][33];
    int vb = blockIdx.x*32, hb = blockIdx.y*32;
    int x = threadIdx.x, y = threadIdx.y;
    for (int j = y; j < 32; j += 8) {
        int v = vb + j;
        t[j][x] = (v < V_) ? vocab[(size_t)v*H_ + hb + x] : 0.f;
    }
    __syncthreads();
    for (int j = y; j < 32; j += 8) {
        int v = vb + x;
        if (v < LDLOG_) vt[(size_t)(hb+j)*LDLOG_ + v] = t[x][j];
    }
}

__global__ void zero_k(float* __restrict__ p, int n) {
    int i = blockIdx.x*256 + threadIdx.x;
    if (i < n) p[i] = 0.f;
}

__global__ void row_softmax_w_k(float* __restrict__ Lg) {
    int r = blockIdx.x;
    float* row = Lg + (size_t)r*LDLOG_;
    __shared__ float red[256];
    float m = -3.4e38f;
    for (int j = threadIdx.x; j < V_+1; j += 256) m = fmaxf(m, row[j]);
    red[threadIdx.x] = m; __syncthreads();
    for (int o = 128; o > 0; o >>= 1) {
        if (threadIdx.x < o) red[threadIdx.x] = fmaxf(red[threadIdx.x], red[threadIdx.x+o]);
        __syncthreads();
    }
    float M = red[0]; __syncthreads();
    float s = 0.f;
    for (int j = threadIdx.x; j < V_+1; j += 256) s += expf(row[j] - M);
    red[threadIdx.x] = s; __syncthreads();
    for (int o = 128; o > 0; o >>= 1) {
        if (threadIdx.x < o) red[threadIdx.x] += red[threadIdx.x+o];
        __syncthreads();
    }
    float inv = 1.f/red[0];
    for (int j = threadIdx.x; j < V_+1; j += 256)
        row[j] = expf(row[j] - M) * inv;
}

__global__ void vtag_eps_k(const float* __restrict__ words, const float* __restrict__ Lg,
                           float* __restrict__ Vt) {
    int i = blockIdx.x*256 + threadIdx.x;
    int r = i >> 8;
    float w = Lg[(size_t)r*LDLOG_ + V_];
    Vt[i] += w * words[i];
}

__global__ void __launch_bounds__(128)
prop_all_k(const float* __restrict__ R, const float* __restrict__ pe,
           float* __restrict__ ps4) {
    int b = blockIdx.x, s = blockIdx.y;
    int p = threadIdx.x >> 5, lane = threadIdx.x & 31;
    const float* instr = R + ((size_t)b*STEPS_ + s)*H_;
    float acc = 0.f;
    for (int h = lane; h < H_; h += 32) acc = fmaf(instr[h], pe[p*H_ + h], acc);
    acc = warp_sum(acc);
    __shared__ float s4[P_];
    if (lane == 0) s4[p] = acc;
    __syncthreads();
    if (threadIdx.x == 0) {
        float m = fmaxf(fmaxf(s4[0], s4[1]), fmaxf(s4[2], s4[3]));
        float e0 = expf(s4[0]-m), e1 = expf(s4[1]-m), e2 = expf(s4[2]-m), e3 = expf(s4[3]-m);
        float inv = 1.f/(e0+e1+e2+e3);
        float* o = ps4 + ((size_t)b*STEPS_ + s)*P_;
        o[0]=e0*inv; o[1]=e1*inv; o[2]=e2*inv; o[3]=e3*inv;
    }
}

#define NODE_BLKS (N_/8)
#define EDGE_BLKS (E_/8)
__global__ void __launch_bounds__(256)
scores_k(const float* __restrict__ Tr, const float* __restrict__ Et,
         const float* __restrict__ R, const float* __restrict__ ps4,
         const float* __restrict__ Wst, const float* __restrict__ Wrel,
         const int* __restrict__ ng, const int* __restrict__ eg,
         float* __restrict__ ns4, float* __restrict__ es4) {
    int bid = blockIdx.x;
    int warp = threadIdx.x >> 5, lane = threadIdx.x & 31;
    if (bid < NODE_BLKS) {
        int n = bid*8 + warp;
        int g = ng[n];
        const float* T = Tr + (size_t)n*3*H_;
        float t0[8], t1[8], t2[8], ws[8];
        #pragma unroll
        for (int q = 0; q < 8; q++) {
            int h = lane + 32*q;
            t0[q] = T[h]; t1[q] = T[H_+h]; t2[q] = T[2*H_+h]; ws[q] = Wst[h];
        }
        float out[STEPS_];
        #pragma unroll
        for (int s = 0; s < STEPS_; s++) {
            const float* pp = ps4 + ((size_t)g*STEPS_ + s)*P_;
            float p0 = pp[0], p1 = pp[1], p2 = pp[2];
            const float* instr = R + ((size_t)g*STEPS_ + s)*H_;
            float acc = 0.f;
            #pragma unroll
            for (int q = 0; q < 8; q++) {
                int h = lane + 32*q;
                float tv = p0*t0[q] + p1*t1[q] + p2*t2[q];
                float x = instr[h]*tv;
                float e = (x > 0.f) ? x : expm1f(x);
                acc = fmaf(e, ws[q], acc);
            }
            out[s] = warp_sum(acc);
        }
        if (lane == 0)
            *reinterpret_cast<float4*>(ns4 + (size_t)n*4) =
                make_float4(out[0], out[1], out[2], out[3]);
    } else {
        int e = (bid - NODE_BLKS)*8 + warp;
        int g = eg[e];
        const float* et = Et + (size_t)e*H_;
        float ev[8], wr[8];
        #pragma unroll
        for (int q = 0; q < 8; q++) {
            int h = lane + 32*q;
            ev[q] = et[h]; wr[q] = Wrel[h];
        }
        float out[STEPS_];
        #pragma unroll
        for (int s = 0; s < STEPS_; s++) {
            const float* instr = R + ((size_t)g*STEPS_ + s)*H_;
            float acc = 0.f;
            #pragma unroll
            for (int q = 0; q < 8; q++) {
                int h = lane + 32*q;
                float x = instr[h]*ev[q];
                float el = (x > 0.f) ? x : expm1f(x);
                acc = fmaf(el, wr[q], acc);
            }
            out[s] = warp_sum(acc);
        }
        if (lane == 0)
            *reinterpret_cast<float4*>(es4 + (size_t)e*4) =
                make_float4(out[0], out[1], out[2], out[3]);
    }
}

__global__ void __launch_bounds__(256)
graph_loop_k(const float* __restrict__ ns4, const float* __restrict__ es4,
             const float* __restrict__ ps4,
             const int* __restrict__ esrc, const int* __restrict__ edst,
             float* __restrict__ dist_out) {
    int g = blockIdx.x, tid = threadIdx.x;
    __shared__ float dist[NPG_], agg[NPG_], red[256];
    __shared__ int lsrc[EPG_], ldst[EPG_];
    __shared__ float4 ns[NPG_];

    int nbase = g*NPG_, ebase = g*EPG_;
    for (int e = tid; e < EPG_; e += 256) {
        lsrc[e] = esrc[ebase + e] - nbase;
        ldst[e] = edst[ebase + e] - nbase;
    }
    if (tid < NPG_) {
        dist[tid] = 1.f/(float)NPG_;
        ns[tid] = *reinterpret_cast<const float4*>(ns4 + (size_t)(nbase + tid)*4);
    }
    __syncthreads();

    for (int s = 0; s < STEPS_; s++) {
        if (tid < NPG_) agg[tid] = 0.f;
        __syncthreads();
        for (int e = tid; e < EPG_; e += 256) {
            float sc = es4[(size_t)(ebase + e)*4 + s];
            atomicAdd(&agg[ldst[e]], dist[lsrc[e]]*sc);
        }
        __syncthreads();

        float nsv = (tid < NPG_) ? ((const float*)&ns[tid])[s] : -3.4e38f;
        float agv = (tid < NPG_) ? agg[tid] : -3.4e38f;
        red[tid] = nsv; __syncthreads();
        for (int o = 128; o > 0; o >>= 1) { if (tid < o) red[tid] = fmaxf(red[tid], red[tid+o]); __syncthreads(); }
        float m1 = red[0]; __syncthreads();
        red[tid] = agv; __syncthreads();
        for (int o = 128; o > 0; o >>= 1) { if (tid < o) red[tid] = fmaxf(red[tid], red[tid+o]); __syncthreads(); }
        float m2 = red[0]; __syncthreads();
        float e1 = (tid < NPG_) ? expf(nsv - m1) : 0.f;
        float e2 = (tid < NPG_) ? expf(agv - m2) : 0.f;
        red[tid] = e1; __syncthreads();
        for (int o = 128; o > 0; o >>= 1) { if (tid < o) red[tid] += red[tid+o]; __syncthreads(); }
        float s1 = red[0]; __syncthreads();
        red[tid] = e2; __syncthreads();
        for (int o = 128; o > 0; o >>= 1) { if (tid < o) red[tid] += red[tid+o]; __syncthreads(); }
        float s2 = red[0]; __syncthreads();
        if (tid < NPG_) {
            float r = ps4[((size_t)g*STEPS_ + s)*P_ + 3];
            dist[tid] = r*(e2/s2) + (1.f - r)*(e1/s1);
        }
        __syncthreads();
    }
    if (tid < NPG_) dist_out[nbase + tid] = dist[tid];
}

__global__ void final_agg_qa_k(const float* __restrict__ na, const float* __restrict__ ps4,
                               const float* __restrict__ dist, const float* __restrict__ Q,
                               float* __restrict__ QA) {
    int g = blockIdx.x, h = threadIdx.x;
    const float* pp = ps4 + ((size_t)g*STEPS_ + (STEPS_-1))*P_;
    float p0 = pp[0], p1 = pp[1], p2 = pp[2];
    float acc = 0.f;
    for (int i = 0; i < NPG_; i++) {
        size_t n = (size_t)g*NPG_ + i;
        const float* a = na + n*3*H_;
        float nf = p0*a[h] + p1*a[H_+h] + p2*a[2*H_+h];
        acc = fmaf(dist[n], nf, acc);
    }
    QA[(size_t)g*2*H_ + h]      = Q[(size_t)g*H_ + h];
    QA[(size_t)g*2*H_ + H_ + h] = acc;
}

// ---------------- launchers ----------------
static inline void tc_gemm(const float* A, int lda, const float* Bm, int ldb,
                           float* C, int ldc, int M, int N, int K,
                           const float* bias, int splitk = 1) {
    dim3 g((N + GB_N - 1)/GB_N, (M + GB_M - 1)/GB_M, splitk);
    mma_gemm_k<<<g, 256, G_SMEM_BYTES>>>(A, lda, Bm, ldb, C, ldc, M, N, K, bias, splitk);
}

extern "C" void kernel_launch(void* const* d_in, const int* in_sizes, int n_in,
                              void* d_out, int out_size) {
    const float* questions     = (const float*)d_in[0];
    const float* node_attrs    = (const float*)d_in[1];
    const float* edge_attrs    = (const float*)d_in[2];
    const float* vocab         = (const float*)d_in[3];
    const float* default_embed = (const float*)d_in[4];
    const float* W_norm        = (const float*)d_in[5];
    const float* lstm_Wih      = (const float*)d_in[6];
    const float* lstm_Whh      = (const float*)d_in[7];
    const float* lstm_bih      = (const float*)d_in[8];
    const float* lstm_bhh      = (const float*)d_in[9];
    const float* rnn_Wih       = (const float*)d_in[10];
    const float* rnn_Whh       = (const float*)d_in[11];
    const float* rnn_bih       = (const float*)d_in[12];
    const float* rnn_bhh       = (const float*)d_in[13];
    const float* prop_embeds   = (const float*)d_in[14];
    const float* Ws_property   = (const float*)d_in[15];
    const float* W_state       = (const float*)d_in[16];
    const float* W_relation    = (const float*)d_in[17];
    const float* lin_W         = (const float*)d_in[18];
    const float* lin_b         = (const float*)d_in[19];
    const int*   lengths       = (const int*)d_in[20];
    const int*   node_graph    = (const int*)d_in[21];
    const int*   edge_graph    = (const int*)d_in[22];
    const int*   edge_src      = (const int*)d_in[23];
    const int*   edge_dst      = (const int*)d_in[24];
    float* out = (float*)d_out;

    cudaFuncSetAttribute(mma_gemm_k, cudaFuncAttributeMaxDynamicSharedMemorySize, G_SMEM_BYTES);

    float* S = nullptr;
    cudaGetSymbolAddress((void**)&S, g_scratch);
    float* Cc   = S + OFF_C;
    float* XW   = S + OFF_XW;
    float* LG   = S + OFF_LOG;
    float* VT   = S + OFF_VT;
    float* XG   = S + OFF_XG;
    float* H0   = S + OFF_H;
    float* Cst  = S + OFF_CS;
    float* H1   = S + OFF_H2;
    float* Rr   = S + OFF_R;
    float* PS4  = S + OFF_PS;
    float* TR   = S + OFF_TR;
    float* ET   = S + OFF_ET;
    float* NS4  = S + OFF_NS4;
    float* ES4  = S + OFF_ES4;
    float* DIST = S + OFF_DIST;
    float* QA   = S + OFF_QA;
    float* WNT  = S + OFF_WNT;
    float* VOCT = S + OFF_VOCT;
    float* WIHT = S + OFF_WIHT;
    float* WHHT = S + OFF_WHHT;

    // 0. one-time layout prep
    build_c_k<<<((V_+1)*H_ + 255)/256, 256>>>(vocab, default_embed, Cc);
    transpose_wn_k<<<dim3(8,8), dim3(32,8)>>>(W_norm, WNT);
    transpose_wn_k<<<dim3(8,8), dim3(32,8)>>>(rnn_Wih, WIHT);
    transpose_wn_k<<<dim3(8,8), dim3(32,8)>>>(rnn_Whh, WHHT);
    vocab_t_k<<<dim3((LDLOG_+31)/32, H_/32), dim3(32,8)>>>(vocab, VOCT);

    // 1. vocab tagging
    tc_gemm(questions, H_, WNT, H_, XW, H_, BL_, H_, H_, nullptr);
    tc_gemm(XW, H_, Cc, H_, LG, LDLOG_, BL_, V_+1, H_, nullptr);
    row_softmax_w_k<<<BL_, 256>>>(LG);
    zero_k<<<(BL_*H_ + 255)/256, 256>>>(VT, BL_*H_);
    tc_gemm(LG, LDLOG_, VOCT, LDLOG_, VT, H_, BL_, H_, V_, nullptr, 4);
    vtag_eps_k<<<BL_*H_/256, 256>>>(questions, LG, VT);

    // 2. LSTM encoder
    tc_gemm(VT, H_, lstm_Wih, H_, XG, 4*H_, BL_, 4*H_, H_, lstm_bih);
    zero_k<<<(2*B_*H_ + 255)/256, 256>>>(H0, 2*B_*H_);
    for (int t = 0; t < L_; t++) {
        const float* hin = (t & 1) ? H1 : H0;
        float* hout      = (t & 1) ? H0 : H1;
        lstm_step_k<<<dim3(16,4), 256>>>(hin, hout, Cst, XG, lstm_Whh, lstm_bhh, lengths, t);
    }

    // 3. fused decoder + attention
    dec_attn_k<<<B_, 256>>>(H0, WIHT, WHHT, rnn_bih, rnn_bhh, VT, lengths, Rr);

    // 4. loop-invariant graph transforms
    for (int p = 0; p < 3; p++)
        tc_gemm(node_attrs + p*H_, 3*H_, Ws_property + (size_t)p*H_*H_, H_,
                TR + p*H_, 3*H_, N_, H_, H_, nullptr);
    tc_gemm(edge_attrs, H_, Ws_property + (size_t)3*H_*H_, H_, ET, H_, E_, H_, H_, nullptr);

    // 5. reasoning
    prop_all_k<<<dim3(B_, STEPS_), 128>>>(Rr, prop_embeds, PS4);
    scores_k<<<NODE_BLKS + EDGE_BLKS, 256>>>(TR, ET, Rr, PS4, W_state, W_relation,
                                             node_graph, edge_graph, NS4, ES4);
    graph_loop_k<<<B_, 256>>>(NS4, ES4, PS4, edge_src, edge_dst, DIST);

    // 6. final aggregation + output projection
    final_agg_qa_k<<<B_, 256>>>(node_attrs, PS4, DIST, H0, QA);
    zero_k<<<(B_*OUT_ + 255)/256, 256>>>(out, B_*OUT_);
    tc_gemm(QA, 2*H_, lin_W, 2*H_, out, OUT_, B_, OUT_, 2*H_, lin_b, 4);
}

// round 11
// speedup vs baseline: 1.0181x; 1.0181x over previous
#include <cuda_runtime.h>
#include <math.h>
#include <stdint.h>

#define B_      256
#define L_      16
#define H_      256
#define V_      5000
#define P_      4
#define NPG_    150
#define DEG_    4
#define EPG_    (NPG_*DEG_)
#define STEPS_  4
#define OUT_    2000
#define N_      (B_*NPG_)
#define E_      (N_*DEG_)
#define BL_     (B_*L_)
#define LDLOG_  5008

// ---------------- scratch arena ----------------
static constexpr size_t SZ_C    = (size_t)(V_+1)*H_;
static constexpr size_t SZ_XW   = (size_t)BL_*H_;
static constexpr size_t SZ_LOG  = (size_t)BL_*LDLOG_;
static constexpr size_t SZ_VT   = (size_t)BL_*H_;
static constexpr size_t SZ_XG   = (size_t)BL_*4*H_;
static constexpr size_t SZ_H    = (size_t)B_*H_;
static constexpr size_t SZ_HINS = (size_t)B_*STEPS_*H_;
static constexpr size_t SZ_TR   = (size_t)N_*3*H_;
static constexpr size_t SZ_ET   = (size_t)E_*H_;

static constexpr size_t OFF_C    = 0;
static constexpr size_t OFF_XW   = OFF_C    + SZ_C;
static constexpr size_t OFF_LOG  = OFF_XW   + SZ_XW;
static constexpr size_t OFF_VT   = OFF_LOG  + SZ_LOG;
static constexpr size_t OFF_XG   = OFF_VT   + SZ_VT;
static constexpr size_t OFF_H    = OFF_XG   + SZ_XG;
static constexpr size_t OFF_CS   = OFF_H    + SZ_H;
static constexpr size_t OFF_H2   = OFF_CS   + SZ_H;
static constexpr size_t OFF_R    = OFF_H2   + SZ_H;
static constexpr size_t OFF_PS   = OFF_R    + SZ_HINS;
static constexpr size_t OFF_TR   = OFF_PS   + (size_t)B_*STEPS_*P_;
static constexpr size_t OFF_ET   = OFF_TR   + SZ_TR;
static constexpr size_t OFF_NS4  = OFF_ET   + SZ_ET;
static constexpr size_t OFF_ES4  = OFF_NS4  + (size_t)N_*4;
static constexpr size_t OFF_DIST = OFF_ES4  + (size_t)E_*4;
static constexpr size_t OFF_QA   = OFF_DIST + N_;
static constexpr size_t OFF_WNT  = OFF_QA   + (size_t)B_*2*H_;
static constexpr size_t OFF_VOCT = OFF_WNT  + (size_t)H_*H_;
static constexpr size_t OFF_WIHT = OFF_VOCT + (size_t)H_*LDLOG_;
static constexpr size_t OFF_WHHT = OFF_WIHT + (size_t)H_*H_;
static constexpr size_t OFF_WSR  = OFF_WHHT + (size_t)H_*H_;          // rounded Ws_property [4,H,H]
static constexpr size_t OFF_LWR  = OFF_WSR  + (size_t)P_*H_*H_;       // rounded lin_W [OUT,2H]
static constexpr size_t TOTAL_SCRATCH = OFF_LWR + (size_t)OUT_*2*H_;

__device__ __align__(16) float g_scratch[TOTAL_SCRATCH];

// ---------------- helpers ----------------
__device__ __forceinline__ float warp_sum(float v) {
    #pragma unroll
    for (int o = 16; o > 0; o >>= 1) v += __shfl_down_sync(0xffffffffu, v, o);
    return v;
}
__device__ __forceinline__ float sigmoidf_(float x) { return 1.f / (1.f + expf(-x)); }
__device__ __forceinline__ uint32_t f2tf32(float x) {
    uint32_t u;
    asm("cvt.rna.tf32.f32 %0, %1;" : "=r"(u) : "f"(x));
    return u;
}
__device__ __forceinline__ float rndtf(float x) { return __uint_as_float(f2tf32(x)); }
__device__ __forceinline__ uint32_t smem_u32(const void* p) {
    uint32_t a;
    asm("{ .reg .u64 t; cvta.to.shared.u64 t, %1; cvt.u32.u64 %0, t; }" : "=r"(a) : "l"(p));
    return a;
}
__device__ __forceinline__ void cp_async16(void* sdst, const void* gsrc, bool pred) {
    uint32_t d = smem_u32(sdst);
    int sz = pred ? 16 : 0;
    asm volatile("cp.async.cg.shared.global [%0], [%1], 16, %2;"
                 :: "r"(d), "l"(gsrc), "r"(sz));
}
__device__ __forceinline__ void cp_commit() {
    asm volatile("cp.async.commit_group;" ::: "memory");
}
template<int N>
__device__ __forceinline__ void cp_wait() {
    asm volatile("cp.async.wait_group %0;" :: "n"(N) : "memory");
}
__device__ __forceinline__ void mma_tf32(float* d, const uint32_t* a, const uint32_t* b) {
    asm volatile(
        "mma.sync.aligned.m16n8k8.row.col.f32.tf32.tf32.f32 "
        "{%0,%1,%2,%3}, {%4,%5,%6,%7}, {%8,%9}, {%0,%1,%2,%3};"
        : "+f"(d[0]), "+f"(d[1]), "+f"(d[2]), "+f"(d[3])
        : "r"(a[0]), "r"(a[1]), "r"(a[2]), "r"(a[3]), "r"(b[0]), "r"(b[1]));
}

// ---------------- tf32 GEMM: CTA 128x128x32, 128 thr, warp 64x64 (2x2) ----------------
// CVTA/CVTB: apply cvt.rna at fragment load (operand not pre-rounded).
// round_c: round output to tf32 in epilogue (only valid with splitk==1).
#define GB_M 128
#define GB_N 128
#define GB_K 32
#define GTS  36
#define GABUF (GB_M*GTS)
#define GBBUF (GB_N*GTS)
#define G_SMEM_BYTES ((2*GABUF + 2*GBBUF)*4)

template<bool CVTA, bool CVTB>
__global__ void __launch_bounds__(128, 2)
mma_gemm_k(const float* __restrict__ A, int lda,
           const float* __restrict__ Bm, int ldb,
           float* __restrict__ C, int ldc,
           int M, int N, int K, const float* __restrict__ bias,
           int splitk, int round_c)
{
    extern __shared__ float smf[];
    float* As = smf;
    float* Bs = smf + 2*GABUF;
    const int tid  = threadIdx.x;
    const int wid  = tid >> 5, lane = tid & 31;
    const int g    = lane >> 2, t4 = lane & 3;
    const int wm   = wid & 1, wn = wid >> 1;
    const int bm   = blockIdx.y * GB_M;
    const int bn   = blockIdx.x * GB_N;

    int kbeg = 0, kend = K;
    if (splitk > 1) {
        int kslen = (((K + splitk - 1) / splitk) + 3) & ~3;
        kbeg  = blockIdx.z * kslen;
        kend  = min(K, kbeg + kslen);
    }

    float acc[4][8][4];
    #pragma unroll
    for (int i = 0; i < 4; i++)
        #pragma unroll
        for (int j = 0; j < 8; j++)
            #pragma unroll
            for (int q = 0; q < 4; q++) acc[i][j][q] = 0.f;

    const int lrow = tid >> 3, lc4 = (tid & 7) << 2;   // 16 rows per pass, 8 passes

    auto issue_chunk = [&](int c) {
        int k0 = kbeg + c * GB_K;
        int buf = c & 1;
        #pragma unroll
        for (int i = 0; i < 8; i++) {
            int row = lrow + i*16;
            int gm = bm + row, gk = k0 + lc4;
            cp_async16(As + buf*GABUF + row*GTS + lc4,
                       A + (size_t)gm*lda + gk, (gm < M) && (gk < kend));
        }
        #pragma unroll
        for (int i = 0; i < 8; i++) {
            int row = lrow + i*16;
            int gn = bn + row, gk = k0 + lc4;
            cp_async16(Bs + buf*GBBUF + row*GTS + lc4,
                       Bm + (size_t)gn*ldb + gk, (gn < N) && (gk < kend));
        }
        cp_commit();
    };

    const int nch = (kend - kbeg + GB_K - 1) / GB_K;
    issue_chunk(0);

    for (int c = 0; c < nch; c++) {
        if (c + 1 < nch) { issue_chunk(c + 1); cp_wait<1>(); }
        else             { cp_wait<0>(); }
        __syncthreads();

        const float* Ab = As + (c & 1)*GABUF;
        const float* Bb = Bs + (c & 1)*GBBUF;
        #pragma unroll
        for (int ks = 0; ks < 4; ks++) {
            uint32_t af[4][4], bf[8][2];
            #pragma unroll
            for (int mt = 0; mt < 4; mt++) {
                int r0 = (wm*64 + mt*16 + g)*GTS + ks*8 + t4;
                if (CVTA) {
                    af[mt][0] = f2tf32(Ab[r0]);
                    af[mt][1] = f2tf32(Ab[r0 + 8*GTS]);
                    af[mt][2] = f2tf32(Ab[r0 + 4]);
                    af[mt][3] = f2tf32(Ab[r0 + 8*GTS + 4]);
                } else {
                    af[mt][0] = __float_as_uint(Ab[r0]);
                    af[mt][1] = __float_as_uint(Ab[r0 + 8*GTS]);
                    af[mt][2] = __float_as_uint(Ab[r0 + 4]);
                    af[mt][3] = __float_as_uint(Ab[r0 + 8*GTS + 4]);
                }
            }
            #pragma unroll
            for (int nt = 0; nt < 8; nt++) {
                int rb = (wn*64 + nt*8 + g)*GTS + ks*8 + t4;
                if (CVTB) {
                    bf[nt][0] = f2tf32(Bb[rb]);
                    bf[nt][1] = f2tf32(Bb[rb + 4]);
                } else {
                    bf[nt][0] = __float_as_uint(Bb[rb]);
                    bf[nt][1] = __float_as_uint(Bb[rb + 4]);
                }
            }
            #pragma unroll
            for (int mt = 0; mt < 4; mt++)
                #pragma unroll
                for (int nt = 0; nt < 8; nt++)
                    mma_tf32(acc[mt][nt], af[mt], bf[nt]);
        }
        __syncthreads();
    }

    const bool addb = (bias != nullptr) && (blockIdx.z == 0);
    #pragma unroll
    for (int mt = 0; mt < 4; mt++) {
        int row0 = bm + wm*64 + mt*16 + g;
        #pragma unroll
        for (int nt = 0; nt < 8; nt++) {
            int col0 = bn + wn*64 + nt*8 + t4*2;
            float b0v = 0.f, b1v = 0.f;
            if (addb) {
                if (col0     < N) b0v = bias[col0];
                if (col0 + 1 < N) b1v = bias[col0+1];
            }
            float v0 = acc[mt][nt][0] + b0v, v1 = acc[mt][nt][1] + b1v;
            float v2 = acc[mt][nt][2] + b0v, v3 = acc[mt][nt][3] + b1v;
            if (splitk > 1) {
                if (row0 < M) {
                    if (col0     < N) atomicAdd(&C[(size_t)row0*ldc + col0    ], v0);
                    if (col0 + 1 < N) atomicAdd(&C[(size_t)row0*ldc + col0 + 1], v1);
                }
                if (row0 + 8 < M) {
                    if (col0     < N) atomicAdd(&C[(size_t)(row0+8)*ldc + col0    ], v2);
                    if (col0 + 1 < N) atomicAdd(&C[(size_t)(row0+8)*ldc + col0 + 1], v3);
                }
            } else {
                if (round_c) { v0 = rndtf(v0); v1 = rndtf(v1); v2 = rndtf(v2); v3 = rndtf(v3); }
                if (row0 < M) {
                    if (col0     < N) C[(size_t)row0*ldc + col0    ] = v0;
                    if (col0 + 1 < N) C[(size_t)row0*ldc + col0 + 1] = v1;
                }
                if (row0 + 8 < M) {
                    if (col0     < N) C[(size_t)(row0+8)*ldc + col0    ] = v2;
                    if (col0 + 1 < N) C[(size_t)(row0+8)*ldc + col0 + 1] = v3;
                }
            }
        }
    }
}

// ---------------- fused LSTM step ----------------
__global__ void __launch_bounds__(256)
lstm_step_k(const float* __restrict__ hin,
            float* __restrict__ hout,
            float* __restrict__ cst,
            const float* __restrict__ Xg,
            const float* __restrict__ Whh,
            const float* __restrict__ bhh,
            const int* __restrict__ lengths, int t)
{
    __shared__ float As[8][64];
    __shared__ float Bs[8][64];
    __shared__ float Cs[64][65];
    const int tid = threadIdx.x;
    const int hh0 = blockIdx.x * 16;
    const int bm  = blockIdx.y * 64;
    const int tx = tid & 15, ty = tid >> 4;

    float acc[4][4];
    #pragma unroll
    for (int i = 0; i < 4; i++)
        #pragma unroll
        for (int j = 0; j < 4; j++) acc[i][j] = 0.f;

    for (int k0 = 0; k0 < H_; k0 += 8) {
        if (tid < 128) {
            int m = tid >> 1, kq = (tid & 1)*4;
            float4 v = *reinterpret_cast<const float4*>(hin + (size_t)(bm+m)*H_ + k0 + kq);
            As[kq+0][m]=v.x; As[kq+1][m]=v.y; As[kq+2][m]=v.z; As[kq+3][m]=v.w;
        } else {
            int it = tid - 128;
            int j = it >> 1, kq = (it & 1)*4;
            int gn = (j >> 4)*H_ + hh0 + (j & 15);
            float4 v = *reinterpret_cast<const float4*>(Whh + (size_t)gn*H_ + k0 + kq);
            Bs[kq+0][j]=v.x; Bs[kq+1][j]=v.y; Bs[kq+2][j]=v.z; Bs[kq+3][j]=v.w;
        }
        __syncthreads();
        #pragma unroll
        for (int k = 0; k < 8; k++) {
            float ar[4], br[4];
            #pragma unroll
            for (int i = 0; i < 4; i++) ar[i] = As[k][ty*4+i];
            #pragma unroll
            for (int j = 0; j < 4; j++) br[j] = Bs[k][tx*4+j];
            #pragma unroll
            for (int i = 0; i < 4; i++)
                #pragma unroll
                for (int j = 0; j < 4; j++)
                    acc[i][j] = fmaf(ar[i], br[j], acc[i][j]);
        }
        __syncthreads();
    }
    #pragma unroll
    for (int i = 0; i < 4; i++)
        #pragma unroll
        for (int j = 0; j < 4; j++)
            Cs[ty*4+i][tx*4+j] = acc[i][j];
    __syncthreads();

    #pragma unroll
    for (int i = 0; i < 4; i++) {
        int cell = i*256 + tid;
        int b_l = cell >> 4, hh_l = cell & 15;
        int b = bm + b_l, hh = hh0 + hh_l;
        const float* xrow = Xg + (size_t)(b*L_ + t)*(4*H_);
        float gi = Cs[b_l][0*16+hh_l] + xrow[hh]        + bhh[hh];
        float gf = Cs[b_l][1*16+hh_l] + xrow[H_+hh]     + bhh[H_+hh];
        float gc = Cs[b_l][2*16+hh_l] + xrow[2*H_+hh]   + bhh[2*H_+hh];
        float go = Cs[b_l][3*16+hh_l] + xrow[3*H_+hh]   + bhh[3*H_+hh];
        size_t idx = (size_t)b*H_ + hh;
        float hold = hin[idx];
        if (t < lengths[b]) {
            float cn = sigmoidf_(gf)*cst[idx] + sigmoidf_(gi)*tanhf(gc);
            cst[idx] = cn;
            hout[idx] = sigmoidf_(go)*tanhf(cn);
        } else {
            hout[idx] = hold;
        }
    }
}

// ---------------- fused decoder RNN + attention ----------------
__global__ void __launch_bounds__(256)
dec_attn_k(const float* __restrict__ Q,
           const float* __restrict__ WihT,
           const float* __restrict__ WhhT,
           const float* __restrict__ bih, const float* __restrict__ bhh,
           const float* __restrict__ Vt,
           const int* __restrict__ lengths,
           float* __restrict__ R)
{
    int b = blockIdx.x, tid = threadIdx.x;
    __shared__ float shh[H_], sQ[H_], sh[H_];
    __shared__ float sV[L_][H_];
    __shared__ float sHins[STEPS_][H_];
    __shared__ float satt[STEPS_][L_];

    shh[tid] = Q[(size_t)b*H_ + tid];
    for (int i = tid; i < L_*H_; i += 256) sV[i>>8][i&255] = Vt[(size_t)b*L_*H_ + i];
    __syncthreads();

    float acc = bih[tid];
    #pragma unroll 8
    for (int k = 0; k < H_; k++) acc = fmaf(shh[k], WihT[(size_t)k*H_ + tid], acc);
    sQ[tid] = acc;
    sh[tid] = 0.f;
    __syncthreads();

    for (int s = 0; s < STEPS_; s++) {
        float v = sQ[tid] + bhh[tid];
        #pragma unroll 8
        for (int k = 0; k < H_; k++) v = fmaf(sh[k], WhhT[(size_t)k*H_ + tid], v);
        v = fmaxf(v, 0.f);
        __syncthreads();
        sh[tid] = v;
        sHins[s][tid] = v;
        __syncthreads();
    }

    int warp = tid >> 5, lane = tid & 31;
    for (int pid = warp; pid < STEPS_*L_; pid += 8) {
        int s = pid >> 4, l = pid & 15;
        float a = 0.f;
        #pragma unroll
        for (int q = 0; q < H_/32; q++) a = fmaf(sHins[s][lane+32*q], sV[l][lane+32*q], a);
        a = warp_sum(a);
        if (lane == 0) satt[s][l] = a;
    }
    __syncthreads();
    if (tid < STEPS_) {
        int len = lengths[b];
        float m = -3.4e38f;
        for (int l = 0; l < len; l++) m = fmaxf(m, satt[tid][l]);
        float s = 0.f;
        for (int l = 0; l < len; l++) { float e = expf(satt[tid][l]-m); satt[tid][l]=e; s+=e; }
        float inv = 1.f/s;
        for (int l = 0; l < L_; l++) satt[tid][l] = (l < len) ? satt[tid][l]*inv : 0.f;
    }
    __syncthreads();
    for (int s = 0; s < STEPS_; s++) {
        float a2 = 0.f;
        #pragma unroll
        for (int l = 0; l < L_; l++) a2 = fmaf(satt[s][l], sV[l][tid], a2);
        R[((size_t)b*STEPS_ + s)*H_ + tid] = a2;
    }
}

// ---------------- small kernels ----------------
__global__ void build_c_k(const float* __restrict__ vocab, const float* __restrict__ de,
                          float* __restrict__ Cc) {
    int i = blockIdx.x*256 + threadIdx.x;
    if (i < (V_+1)*H_) Cc[i] = rndtf((i < V_*H_) ? vocab[i] : de[i - (size_t)V_*H_]);
}

__global__ void round_copy_k(const float* __restrict__ src, float* __restrict__ dst, int n) {
    int i = blockIdx.x*256 + threadIdx.x;
    if (i < n) dst[i] = rndtf(src[i]);
}

__global__ void transpose_wn_k(const float* __restrict__ W, float* __restrict__ WT, int do_round) {
    __shared__ float t[32][33];
    int rb = blockIdx.y*32, cb = blockIdx.x*32;
    int x = threadIdx.x, y = threadIdx.y;
    for (int j = y; j < 32; j += 8) t[j][x] = W[(size_t)(rb+j)*H_ + cb + x];
    __syncthreads();
    for (int j = y; j < 32; j += 8) {
        float v = t[x][j];
        WT[(size_t)(cb+j)*H_ + rb + x] = do_round ? rndtf(v) : v;
    }
}

__global__ void vocab_t_k(const float* __restrict__ vocab, float* __restrict__ vt) {
    __shared__ float t[32][33];
    int vb = blockIdx.x*32, hb = blockIdx.y*32;
    int x = threadIdx.x, y = threadIdx.y;
    for (int j = y; j < 32; j += 8) {
        int v = vb + j;
        t[j][x] = (v < V_) ? vocab[(size_t)v*H_ + hb + x] : 0.f;
    }
    __syncthreads();
    for (int j = y; j < 32; j += 8) {
        int v = vb + x;
        if (v < LDLOG_) vt[(size_t)(hb+j)*LDLOG_ + v] = rndtf(t[x][j]);
    }
}

__global__ void zero_k(float* __restrict__ p, int n) {
    int i = blockIdx.x*256 + threadIdx.x;
    if (i < n) p[i] = 0.f;
}

// row softmax; final write pre-rounded to tf32 (GEMM3 reads raw bits)
__global__ void row_softmax_w_k(float* __restrict__ Lg) {
    int r = blockIdx.x;
    float* row = Lg + (size_t)r*LDLOG_;
    __shared__ float red[256];
    float m = -3.4e38f;
    for (int j = threadIdx.x; j < V_+1; j += 256) m = fmaxf(m, row[j]);
    red[threadIdx.x] = m; __syncthreads();
    for (int o = 128; o > 0; o >>= 1) {
        if (threadIdx.x < o) red[threadIdx.x] = fmaxf(red[threadIdx.x], red[threadIdx.x+o]);
        __syncthreads();
    }
    float M = red[0]; __syncthreads();
    float s = 0.f;
    for (int j = threadIdx.x; j < V_+1; j += 256) s += expf(row[j] - M);
    red[threadIdx.x] = s; __syncthreads();
    for (int o = 128; o > 0; o >>= 1) {
        if (threadIdx.x < o) red[threadIdx.x] += red[threadIdx.x+o];
        __syncthreads();
    }
    float inv = 1.f/red[0];
    for (int j = threadIdx.x; j < V_+1; j += 256)
        row[j] = rndtf(expf(row[j] - M) * inv);
}

__global__ void vtag_eps_k(const float* __restrict__ words, const float* __restrict__ Lg,
                           float* __restrict__ Vt) {
    int i = blockIdx.x*256 + threadIdx.x;
    int r = i >> 8;
    float w = Lg[(size_t)r*LDLOG_ + V_];
    Vt[i] += w * words[i];
}

__global__ void __launch_bounds__(128)
prop_all_k(const float* __restrict__ R, const float* __restrict__ pe,
           float* __restrict__ ps4) {
    int b = blockIdx.x, s = blockIdx.y;
    int p = threadIdx.x >> 5, lane = threadIdx.x & 31;
    const float* instr = R + ((size_t)b*STEPS_ + s)*H_;
    float acc = 0.f;
    for (int h = lane; h < H_; h += 32) acc = fmaf(instr[h], pe[p*H_ + h], acc);
    acc = warp_sum(acc);
    __shared__ float s4[P_];
    if (lane == 0) s4[p] = acc;
    __syncthreads();
    if (threadIdx.x == 0) {
        float m = fmaxf(fmaxf(s4[0], s4[1]), fmaxf(s4[2], s4[3]));
        float e0 = expf(s4[0]-m), e1 = expf(s4[1]-m), e2 = expf(s4[2]-m), e3 = expf(s4[3]-m);
        float inv = 1.f/(e0+e1+e2+e3);
        float* o = ps4 + ((size_t)b*STEPS_ + s)*P_;
        o[0]=e0*inv; o[1]=e1*inv; o[2]=e2*inv; o[3]=e3*inv;
    }
}

#define NODE_BLKS (N_/8)
#define EDGE_BLKS (E_/8)
__global__ void __launch_bounds__(256)
scores_k(const float* __restrict__ Tr, const float* __restrict__ Et,
         const float* __restrict__ R, const float* __restrict__ ps4,
         const float* __restrict__ Wst, const float* __restrict__ Wrel,
         const int* __restrict__ ng, const int* __restrict__ eg,
         float* __restrict__ ns4, float* __restrict__ es4) {
    int bid = blockIdx.x;
    int warp = threadIdx.x >> 5, lane = threadIdx.x & 31;
    if (bid < NODE_BLKS) {
        int n = bid*8 + warp;
        int g = ng[n];
        const float* T = Tr + (size_t)n*3*H_;
        float t0[8], t1[8], t2[8], ws[8];
        #pragma unroll
        for (int q = 0; q < 8; q++) {
            int h = lane + 32*q;
            t0[q] = T[h]; t1[q] = T[H_+h]; t2[q] = T[2*H_+h]; ws[q] = Wst[h];
        }
        float out[STEPS_];
        #pragma unroll
        for (int s = 0; s < STEPS_; s++) {
            const float* pp = ps4 + ((size_t)g*STEPS_ + s)*P_;
            float p0 = pp[0], p1 = pp[1], p2 = pp[2];
            const float* instr = R + ((size_t)g*STEPS_ + s)*H_;
            float acc = 0.f;
            #pragma unroll
            for (int q = 0; q < 8; q++) {
                int h = lane + 32*q;
                float tv = p0*t0[q] + p1*t1[q] + p2*t2[q];
                float x = instr[h]*tv;
                float e = (x > 0.f) ? x : expm1f(x);
                acc = fmaf(e, ws[q], acc);
            }
            out[s] = warp_sum(acc);
        }
        if (lane == 0)
            *reinterpret_cast<float4*>(ns4 + (size_t)n*4) =
                make_float4(out[0], out[1], out[2], out[3]);
    } else {
        int e = (bid - NODE_BLKS)*8 + warp;
        int g = eg[e];
        const float* et = Et + (size_t)e*H_;
        float ev[8], wr[8];
        #pragma unroll
        for (int q = 0; q < 8; q++) {
            int h = lane + 32*q;
            ev[q] = et[h]; wr[q] = Wrel[h];
        }
        float out[STEPS_];
        #pragma unroll
        for (int s = 0; s < STEPS_; s++) {
            const float* instr = R + ((size_t)g*STEPS_ + s)*H_;
            float acc = 0.f;
            #pragma unroll
            for (int q = 0; q < 8; q++) {
                int h = lane + 32*q;
                float x = instr[h]*ev[q];
                float el = (x > 0.f) ? x : expm1f(x);
                acc = fmaf(el, wr[q], acc);
            }
            out[s] = warp_sum(acc);
        }
        if (lane == 0)
            *reinterpret_cast<float4*>(es4 + (size_t)e*4) =
                make_float4(out[0], out[1], out[2], out[3]);
    }
}

__global__ void __launch_bounds__(256)
graph_loop_k(const float* __restrict__ ns4, const float* __restrict__ es4,
             const float* __restrict__ ps4,
             const int* __restrict__ esrc, const int* __restrict__ edst,
             float* __restrict__ dist_out) {
    int g = blockIdx.x, tid = threadIdx.x;
    __shared__ float dist[NPG_], agg[NPG_], red[256];
    __shared__ int lsrc[EPG_], ldst[EPG_];
    __shared__ float4 ns[NPG_];

    int nbase = g*NPG_, ebase = g*EPG_;
    for (int e = tid; e < EPG_; e += 256) {
        lsrc[e] = esrc[ebase + e] - nbase;
        ldst[e] = edst[ebase + e] - nbase;
    }
    if (tid < NPG_) {
        dist[tid] = 1.f/(float)NPG_;
        ns[tid] = *reinterpret_cast<const float4*>(ns4 + (size_t)(nbase + tid)*4);
    }
    __syncthreads();

    for (int s = 0; s < STEPS_; s++) {
        if (tid < NPG_) agg[tid] = 0.f;
        __syncthreads();
        for (int e = tid; e < EPG_; e += 256) {
            float sc = es4[(size_t)(ebase + e)*4 + s];
            atomicAdd(&agg[ldst[e]], dist[lsrc[e]]*sc);
        }
        __syncthreads();

        float nsv = (tid < NPG_) ? ((const float*)&ns[tid])[s] : -3.4e38f;
        float agv = (tid < NPG_) ? agg[tid] : -3.4e38f;
        red[tid] = nsv; __syncthreads();
        for (int o = 128; o > 0; o >>= 1) { if (tid < o) red[tid] = fmaxf(red[tid], red[tid+o]); __syncthreads(); }
        float m1 = red[0]; __syncthreads();
        red[tid] = agv; __syncthreads();
        for (int o = 128; o > 0; o >>= 1) { if (tid < o) red[tid] = fmaxf(red[tid], red[tid+o]); __syncthreads(); }
        float m2 = red[0]; __syncthreads();
        float e1 = (tid < NPG_) ? expf(nsv - m1) : 0.f;
        float e2 = (tid < NPG_) ? expf(agv - m2) : 0.f;
        red[tid] = e1; __syncthreads();
        for (int o = 128; o > 0; o >>= 1) { if (tid < o) red[tid] += red[tid+o]; __syncthreads(); }
        float s1 = red[0]; __syncthreads();
        red[tid] = e2; __syncthreads();
        for (int o = 128; o > 0; o >>= 1) { if (tid < o) red[tid] += red[tid+o]; __syncthreads(); }
        float s2 = red[0]; __syncthreads();
        if (tid < NPG_) {
            float r = ps4[((size_t)g*STEPS_ + s)*P_ + 3];
            dist[tid] = r*(e2/s2) + (1.f - r)*(e1/s1);
        }
        __syncthreads();
    }
    if (tid < NPG_) dist_out[nbase + tid] = dist[tid];
}

// QA written pre-rounded (out-GEMM reads raw bits)
__global__ void final_agg_qa_k(const float* __restrict__ na, const float* __restrict__ ps4,
                               const float* __restrict__ dist, const float* __restrict__ Q,
                               float* __restrict__ QA) {
    int g = blockIdx.x, h = threadIdx.x;
    const float* pp = ps4 + ((size_t)g*STEPS_ + (STEPS_-1))*P_;
    float p0 = pp[0], p1 = pp[1], p2 = pp[2];
    float acc = 0.f;
    for (int i = 0; i < NPG_; i++) {
        size_t n = (size_t)g*NPG_ + i;
        const float* a = na + n*3*H_;
        float nf = p0*a[h] + p1*a[H_+h] + p2*a[2*H_+h];
        acc = fmaf(dist[n], nf, acc);
    }
    QA[(size_t)g*2*H_ + h]      = rndtf(Q[(size_t)g*H_ + h]);
    QA[(size_t)g*2*H_ + H_ + h] = rndtf(acc);
}

// ---------------- launchers ----------------
static inline void tc_gemm(const float* A, int lda, const float* Bm, int ldb,
                           float* C, int ldc, int M, int N, int K,
                           const float* bias, int splitk,
                           int cvta, int cvtb, int round_c) {
    dim3 g((N + GB_N - 1)/GB_N, (M + GB_M - 1)/GB_M, splitk);
    if (cvta && cvtb)
        mma_gemm_k<true,true><<<g, 128, G_SMEM_BYTES>>>(A, lda, Bm, ldb, C, ldc, M, N, K, bias, splitk, round_c);
    else if (cvta)
        mma_gemm_k<true,false><<<g, 128, G_SMEM_BYTES>>>(A, lda, Bm, ldb, C, ldc, M, N, K, bias, splitk, round_c);
    else
        mma_gemm_k<false,false><<<g, 128, G_SMEM_BYTES>>>(A, lda, Bm, ldb, C, ldc, M, N, K, bias, splitk, round_c);
}

extern "C" void kernel_launch(void* const* d_in, const int* in_sizes, int n_in,
                              void* d_out, int out_size) {
    const float* questions     = (const float*)d_in[0];
    const float* node_attrs    = (const float*)d_in[1];
    const float* edge_attrs    = (const float*)d_in[2];
    const float* vocab         = (const float*)d_in[3];
    const float* default_embed = (const float*)d_in[4];
    const float* W_norm        = (const float*)d_in[5];
    const float* lstm_Wih      = (const float*)d_in[6];
    const float* lstm_Whh      = (const float*)d_in[7];
    const float* lstm_bih      = (const float*)d_in[8];
    const float* lstm_bhh      = (const float*)d_in[9];
    const float* rnn_Wih       = (const float*)d_in[10];
    const float* rnn_Whh       = (const float*)d_in[11];
    const float* rnn_bih       = (const float*)d_in[12];
    const float* rnn_bhh       = (const float*)d_in[13];
    const float* prop_embeds   = (const float*)d_in[14];
    const float* Ws_property   = (const float*)d_in[15];
    const float* W_state       = (const float*)d_in[16];
    const float* W_relation    = (const float*)d_in[17];
    const float* lin_W         = (const float*)d_in[18];
    const float* lin_b         = (const float*)d_in[19];
    const int*   lengths       = (const int*)d_in[20];
    const int*   node_graph    = (const int*)d_in[21];
    const int*   edge_graph    = (const int*)d_in[22];
    const int*   edge_src      = (const int*)d_in[23];
    const int*   edge_dst      = (const int*)d_in[24];
    float* out = (float*)d_out;

    cudaFuncSetAttribute(mma_gemm_k<true,true>,   cudaFuncAttributeMaxDynamicSharedMemorySize, G_SMEM_BYTES);
    cudaFuncSetAttribute(mma_gemm_k<true,false>,  cudaFuncAttributeMaxDynamicSharedMemorySize, G_SMEM_BYTES);
    cudaFuncSetAttribute(mma_gemm_k<false,false>, cudaFuncAttributeMaxDynamicSharedMemorySize, G_SMEM_BYTES);

    float* S = nullptr;
    cudaGetSymbolAddress((void**)&S, g_scratch);
    float* Cc   = S + OFF_C;
    float* XW   = S + OFF_XW;
    float* LG   = S + OFF_LOG;
    float* VT   = S + OFF_VT;
    float* XG   = S + OFF_XG;
    float* H0   = S + OFF_H;
    float* Cst  = S + OFF_CS;
    float* H1   = S + OFF_H2;
    float* Rr   = S + OFF_R;
    float* PS4  = S + OFF_PS;
    float* TR   = S + OFF_TR;
    float* ET   = S + OFF_ET;
    float* NS4  = S + OFF_NS4;
    float* ES4  = S + OFF_ES4;
    float* DIST = S + OFF_DIST;
    float* QA   = S + OFF_QA;
    float* WNT  = S + OFF_WNT;
    float* VOCT = S + OFF_VOCT;
    float* WIHT = S + OFF_WIHT;
    float* WHHT = S + OFF_WHHT;
    float* WSR  = S + OFF_WSR;
    float* LWR  = S + OFF_LWR;

    // 0. one-time layout prep (pre-rounded where operand feeds a raw-bit GEMM)
    build_c_k<<<((V_+1)*H_ + 255)/256, 256>>>(vocab, default_embed, Cc);
    transpose_wn_k<<<dim3(8,8), dim3(32,8)>>>(W_norm, WNT, 1);
    transpose_wn_k<<<dim3(8,8), dim3(32,8)>>>(rnn_Wih, WIHT, 0);
    transpose_wn_k<<<dim3(8,8), dim3(32,8)>>>(rnn_Whh, WHHT, 0);
    vocab_t_k<<<dim3((LDLOG_+31)/32, H_/32), dim3(32,8)>>>(vocab, VOCT);
    round_copy_k<<<(P_*H_*H_ + 255)/256, 256>>>(Ws_property, WSR, P_*H_*H_);
    round_copy_k<<<(OUT_*2*H_ + 255)/256, 256>>>(lin_W, LWR, OUT_*2*H_);

    // 1. vocab tagging
    tc_gemm(questions, H_, WNT, H_, XW, H_, BL_, H_, H_, nullptr, 1, 1, 0, 1);   // round XW
    tc_gemm(XW, H_, Cc, H_, LG, LDLOG_, BL_, V_+1, H_, nullptr, 1, 0, 0, 0);
    row_softmax_w_k<<<BL_, 256>>>(LG);   // writes rounded probs
    zero_k<<<(BL_*H_ + 255)/256, 256>>>(VT, BL_*H_);
    tc_gemm(LG, LDLOG_, VOCT, LDLOG_, VT, H_, BL_, H_, V_, nullptr, 4, 0, 0, 0);
    vtag_eps_k<<<BL_*H_/256, 256>>>(questions, LG, VT);

    // 2. LSTM encoder
    tc_gemm(VT, H_, lstm_Wih, H_, XG, 4*H_, BL_, 4*H_, H_, lstm_bih, 1, 1, 1, 0);
    zero_k<<<(2*B_*H_ + 255)/256, 256>>>(H0, 2*B_*H_);
    for (int t = 0; t < L_; t++) {
        const float* hin = (t & 1) ? H1 : H0;
        float* hout      = (t & 1) ? H0 : H1;
        lstm_step_k<<<dim3(16,4), 256>>>(hin, hout, Cst, XG, lstm_Whh, lstm_bhh, lengths, t);
    }

    // 3. fused decoder + attention
    dec_attn_k<<<B_, 256>>>(H0, WIHT, WHHT, rnn_bih, rnn_bhh, VT, lengths, Rr);

    // 4. loop-invariant graph transforms
    for (int p = 0; p < 3; p++)
        tc_gemm(node_attrs + p*H_, 3*H_, WSR + (size_t)p*H_*H_, H_,
                TR + p*H_, 3*H_, N_, H_, H_, nullptr, 1, 1, 0, 0);
    tc_gemm(edge_attrs, H_, WSR + (size_t)3*H_*H_, H_, ET, H_, E_, H_, H_, nullptr, 1, 1, 0, 0);

    // 5. reasoning
    prop_all_k<<<dim3(B_, STEPS_), 128>>>(Rr, prop_embeds, PS4);
    scores_k<<<NODE_BLKS + EDGE_BLKS, 256>>>(TR, ET, Rr, PS4, W_state, W_relation,
                                             node_graph, edge_graph, NS4, ES4);
    graph_loop_k<<<B_, 256>>>(NS4, ES4, PS4, edge_src, edge_dst, DIST);

    // 6. final aggregation + output projection
    final_agg_qa_k<<<B_, 256>>>(node_attrs, PS4, DIST, H0, QA);   // writes rounded QA
    zero_k<<<(B_*OUT_ + 255)/256, 256>>>(out, B_*OUT_);
    tc_gemm(QA, 2*H_, LWR, 2*H_, out, OUT_, B_, OUT_, 2*H_, lin_b, 4, 0, 0, 0);
}

// round 12
// speedup vs baseline: 1.0964x; 1.0769x over previous
#include <cuda_runtime.h>
#include <math.h>
#include <stdint.h>

#define B_      256
#define L_      16
#define H_      256
#define V_      5000
#define P_      4
#define NPG_    150
#define DEG_    4
#define EPG_    (NPG_*DEG_)
#define STEPS_  4
#define OUT_    2000
#define N_      (B_*NPG_)
#define E_      (N_*DEG_)
#define BL_     (B_*L_)
#define LDLOG_  5008

// ---------------- scratch arena ----------------
static constexpr size_t SZ_C    = (size_t)(V_+1)*H_;
static constexpr size_t SZ_XW   = (size_t)BL_*H_;
static constexpr size_t SZ_LOG  = (size_t)BL_*LDLOG_;
static constexpr size_t SZ_VT   = (size_t)BL_*H_;
static constexpr size_t SZ_XG   = (size_t)BL_*4*H_;
static constexpr size_t SZ_H    = (size_t)B_*H_;
static constexpr size_t SZ_HINS = (size_t)B_*STEPS_*H_;
static constexpr size_t SZ_TR   = (size_t)N_*3*H_;
static constexpr size_t SZ_ET   = (size_t)E_*H_;

static constexpr size_t OFF_C    = 0;
static constexpr size_t OFF_XW   = OFF_C    + SZ_C;
static constexpr size_t OFF_LOG  = OFF_XW   + SZ_XW;
static constexpr size_t OFF_VT   = OFF_LOG  + SZ_LOG;
static constexpr size_t OFF_XG   = OFF_VT   + SZ_VT;
static constexpr size_t OFF_H    = OFF_XG   + SZ_XG;
static constexpr size_t OFF_CS   = OFF_H    + SZ_H;
static constexpr size_t OFF_H2   = OFF_CS   + SZ_H;
static constexpr size_t OFF_R    = OFF_H2   + SZ_H;
static constexpr size_t OFF_PS   = OFF_R    + SZ_HINS;
static constexpr size_t OFF_TR   = OFF_PS   + (size_t)B_*STEPS_*P_;
static constexpr size_t OFF_ET   = OFF_TR   + SZ_TR;
static constexpr size_t OFF_NS4  = OFF_ET   + SZ_ET;
static constexpr size_t OFF_ES4  = OFF_NS4  + (size_t)N_*4;
static constexpr size_t OFF_DIST = OFF_ES4  + (size_t)E_*4;
static constexpr size_t OFF_QA   = OFF_DIST + N_;
static constexpr size_t OFF_WNT  = OFF_QA   + (size_t)B_*2*H_;
static constexpr size_t OFF_VOCT = OFF_WNT  + (size_t)H_*H_;
static constexpr size_t OFF_WIHT = OFF_VOCT + (size_t)H_*LDLOG_;
static constexpr size_t OFF_WHHT = OFF_WIHT + (size_t)H_*H_;
static constexpr size_t TOTAL_SCRATCH = OFF_WHHT + (size_t)H_*H_;

__device__ __align__(16) float g_scratch[TOTAL_SCRATCH];

// ---------------- helpers ----------------
__device__ __forceinline__ float warp_sum(float v) {
    #pragma unroll
    for (int o = 16; o > 0; o >>= 1) v += __shfl_down_sync(0xffffffffu, v, o);
    return v;
}
__device__ __forceinline__ float sigmoidf_(float x) { return 1.f / (1.f + expf(-x)); }
__device__ __forceinline__ uint32_t f2tf32(float x) {
    uint32_t u;
    asm("cvt.rna.tf32.f32 %0, %1;" : "=r"(u) : "f"(x));
    return u;
}
__device__ __forceinline__ uint32_t smem_u32(const void* p) {
    uint32_t a;
    asm("{ .reg .u64 t; cvta.to.shared.u64 t, %1; cvt.u32.u64 %0, t; }" : "=r"(a) : "l"(p));
    return a;
}
__device__ __forceinline__ void cp_async16(void* sdst, const void* gsrc, bool pred) {
    uint32_t d = smem_u32(sdst);
    int sz = pred ? 16 : 0;
    asm volatile("cp.async.cg.shared.global [%0], [%1], 16, %2;"
                 :: "r"(d), "l"(gsrc), "r"(sz));
}
__device__ __forceinline__ void cp_commit() {
    asm volatile("cp.async.commit_group;" ::: "memory");
}
template<int N>
__device__ __forceinline__ void cp_wait() {
    asm volatile("cp.async.wait_group %0;" :: "n"(N) : "memory");
}
__device__ __forceinline__ void mma_tf32(float* d, const uint32_t* a, const uint32_t* b) {
    asm volatile(
        "mma.sync.aligned.m16n8k8.row.col.f32.tf32.tf32.f32 "
        "{%0,%1,%2,%3}, {%4,%5,%6,%7}, {%8,%9}, {%0,%1,%2,%3};"
        : "+f"(d[0]), "+f"(d[1]), "+f"(d[2]), "+f"(d[3])
        : "r"(a[0]), "r"(a[1]), "r"(a[2]), "r"(a[3]), "r"(b[0]), "r"(b[1]));
}

// ---------------- tf32 GEMM: CTA 128x128x32, 128 thr, warp 64x64 (2x2) ----------------
#define GB_M 128
#define GB_N 128
#define GB_K 32
#define GTS  36
#define GABUF (GB_M*GTS)
#define GBBUF (GB_N*GTS)
#define G_SMEM_BYTES ((2*GABUF + 2*GBBUF)*4)

__global__ void __launch_bounds__(128, 2)
mma_gemm_k(const float* __restrict__ A, int lda,
           const float* __restrict__ Bm, int ldb,
           float* __restrict__ C, int ldc,
           int M, int N, int K, const float* __restrict__ bias, int splitk)
{
    extern __shared__ float smf[];
    float* As = smf;
    float* Bs = smf + 2*GABUF;
    const int tid  = threadIdx.x;
    const int wid  = tid >> 5, lane = tid & 31;
    const int g    = lane >> 2, t4 = lane & 3;
    const int wm   = wid & 1, wn = wid >> 1;
    const int bm   = blockIdx.y * GB_M;
    const int bn   = blockIdx.x * GB_N;

    int kbeg = 0, kend = K;
    if (splitk > 1) {
        int kslen = (((K + splitk - 1) / splitk) + 3) & ~3;
        kbeg  = blockIdx.z * kslen;
        kend  = min(K, kbeg + kslen);
    }

    float acc[4][8][4];
    #pragma unroll
    for (int i = 0; i < 4; i++)
        #pragma unroll
        for (int j = 0; j < 8; j++)
            #pragma unroll
            for (int q = 0; q < 4; q++) acc[i][j][q] = 0.f;

    const int lrow = tid >> 3, lc4 = (tid & 7) << 2;

    auto issue_chunk = [&](int c) {
        int k0 = kbeg + c * GB_K;
        int buf = c & 1;
        #pragma unroll
        for (int i = 0; i < 8; i++) {
            int row = lrow + i*16;
            int gm = bm + row, gk = k0 + lc4;
            cp_async16(As + buf*GABUF + row*GTS + lc4,
                       A + (size_t)gm*lda + gk, (gm < M) && (gk < kend));
        }
        #pragma unroll
        for (int i = 0; i < 8; i++) {
            int row = lrow + i*16;
            int gn = bn + row, gk = k0 + lc4;
            cp_async16(Bs + buf*GBBUF + row*GTS + lc4,
                       Bm + (size_t)gn*ldb + gk, (gn < N) && (gk < kend));
        }
        cp_commit();
    };

    const int nch = (kend - kbeg + GB_K - 1) / GB_K;
    issue_chunk(0);

    for (int c = 0; c < nch; c++) {
        if (c + 1 < nch) { issue_chunk(c + 1); cp_wait<1>(); }
        else             { cp_wait<0>(); }
        __syncthreads();

        const float* Ab = As + (c & 1)*GABUF;
        const float* Bb = Bs + (c & 1)*GBBUF;
        #pragma unroll
        for (int ks = 0; ks < 4; ks++) {
            uint32_t af[4][4], bf[8][2];
            #pragma unroll
            for (int mt = 0; mt < 4; mt++) {
                int r0 = (wm*64 + mt*16 + g)*GTS + ks*8 + t4;
                af[mt][0] = f2tf32(Ab[r0]);
                af[mt][1] = f2tf32(Ab[r0 + 8*GTS]);
                af[mt][2] = f2tf32(Ab[r0 + 4]);
                af[mt][3] = f2tf32(Ab[r0 + 8*GTS + 4]);
            }
            #pragma unroll
            for (int nt = 0; nt < 8; nt++) {
                int rb = (wn*64 + nt*8 + g)*GTS + ks*8 + t4;
                bf[nt][0] = f2tf32(Bb[rb]);
                bf[nt][1] = f2tf32(Bb[rb + 4]);
            }
            #pragma unroll
            for (int mt = 0; mt < 4; mt++)
                #pragma unroll
                for (int nt = 0; nt < 8; nt++)
                    mma_tf32(acc[mt][nt], af[mt], bf[nt]);
        }
        __syncthreads();
    }

    const bool addb = (bias != nullptr) && (blockIdx.z == 0);
    #pragma unroll
    for (int mt = 0; mt < 4; mt++) {
        int row0 = bm + wm*64 + mt*16 + g;
        #pragma unroll
        for (int nt = 0; nt < 8; nt++) {
            int col0 = bn + wn*64 + nt*8 + t4*2;
            float b0v = 0.f, b1v = 0.f;
            if (addb) {
                if (col0     < N) b0v = bias[col0];
                if (col0 + 1 < N) b1v = bias[col0+1];
            }
            if (splitk > 1) {
                if (row0 < M) {
                    if (col0     < N) atomicAdd(&C[(size_t)row0*ldc + col0    ], acc[mt][nt][0] + b0v);
                    if (col0 + 1 < N) atomicAdd(&C[(size_t)row0*ldc + col0 + 1], acc[mt][nt][1] + b1v);
                }
                if (row0 + 8 < M) {
                    if (col0     < N) atomicAdd(&C[(size_t)(row0+8)*ldc + col0    ], acc[mt][nt][2] + b0v);
                    if (col0 + 1 < N) atomicAdd(&C[(size_t)(row0+8)*ldc + col0 + 1], acc[mt][nt][3] + b1v);
                }
            } else {
                if (row0 < M) {
                    if (col0     < N) C[(size_t)row0*ldc + col0    ] = acc[mt][nt][0] + b0v;
                    if (col0 + 1 < N) C[(size_t)row0*ldc + col0 + 1] = acc[mt][nt][1] + b1v;
                }
                if (row0 + 8 < M) {
                    if (col0     < N) C[(size_t)(row0+8)*ldc + col0    ] = acc[mt][nt][2] + b0v;
                    if (col0 + 1 < N) C[(size_t)(row0+8)*ldc + col0 + 1] = acc[mt][nt][3] + b1v;
                }
            }
        }
    }
}

// ---------------- tensor-core fused LSTM step ----------------
// CTA: 64 batches x 128 gathered cols (32 hh x 4 gates). Grid (H/32, B/64) = (8,4).
// 128 thr, warps 2x2, warp tile 32x64. Gates fused via SMEM exchange.
#define LB_M 64
#define LB_N 128
#define LTS  36
#define LABUF (LB_M*LTS)
#define LBBUF (LB_N*LTS)
#define L_SMEM_BYTES ((2*LABUF + 2*LBBUF)*4)   // 55296; Cs (64x132x4=33792) reuses this

__global__ void __launch_bounds__(128, 2)
lstm_mma_k(const float* __restrict__ hin,
           float* __restrict__ hout,
           float* __restrict__ cst,
           const float* __restrict__ Xg,
           const float* __restrict__ Whh,
           const float* __restrict__ bhh,
           const int* __restrict__ lengths, int t)
{
    extern __shared__ float smf[];
    float* As = smf;
    float* Bs = smf + 2*LABUF;
    float* Cs = smf;                 // reused after mainloop: [64][132]
    const int tid = threadIdx.x;
    const int wid = tid >> 5, lane = tid & 31;
    const int g   = lane >> 2, t4 = lane & 3;
    const int wm  = wid & 1, wn = wid >> 1;
    const int hh0 = blockIdx.x * 32;
    const int bm  = blockIdx.y * LB_M;

    float acc[2][8][4];
    #pragma unroll
    for (int i = 0; i < 2; i++)
        #pragma unroll
        for (int j = 0; j < 8; j++)
            #pragma unroll
            for (int q = 0; q < 4; q++) acc[i][j][q] = 0.f;

    const int lrow = tid >> 3, lc4 = (tid & 7) << 2;

    auto issue_chunk = [&](int c) {
        int k0 = c * GB_K;
        int buf = c & 1;
        #pragma unroll
        for (int i = 0; i < 4; i++) {            // A: 64 rows
            int row = lrow + i*16;
            cp_async16(As + buf*LABUF + row*LTS + lc4,
                       hin + (size_t)(bm + row)*H_ + k0 + lc4, true);
        }
        #pragma unroll
        for (int i = 0; i < 8; i++) {            // B: 128 gathered rows of Whh
            int row = lrow + i*16;
            int gn = (row >> 5)*H_ + hh0 + (row & 31);
            cp_async16(Bs + buf*LBBUF + row*LTS + lc4,
                       Whh + (size_t)gn*H_ + k0 + lc4, true);
        }
        cp_commit();
    };

    const int nch = H_ / GB_K;   // 8
    issue_chunk(0);
    for (int c = 0; c < nch; c++) {
        if (c + 1 < nch) { issue_chunk(c + 1); cp_wait<1>(); }
        else             { cp_wait<0>(); }
        __syncthreads();
        const float* Ab = As + (c & 1)*LABUF;
        const float* Bb = Bs + (c & 1)*LBBUF;
        #pragma unroll
        for (int ks = 0; ks < 4; ks++) {
            uint32_t af[2][4], bf[8][2];
            #pragma unroll
            for (int mt = 0; mt < 2; mt++) {
                int r0 = (wm*32 + mt*16 + g)*LTS + ks*8 + t4;
                af[mt][0] = f2tf32(Ab[r0]);
                af[mt][1] = f2tf32(Ab[r0 + 8*LTS]);
                af[mt][2] = f2tf32(Ab[r0 + 4]);
                af[mt][3] = f2tf32(Ab[r0 + 8*LTS + 4]);
            }
            #pragma unroll
            for (int nt = 0; nt < 8; nt++) {
                int rb = (wn*64 + nt*8 + g)*LTS + ks*8 + t4;
                bf[nt][0] = f2tf32(Bb[rb]);
                bf[nt][1] = f2tf32(Bb[rb + 4]);
            }
            #pragma unroll
            for (int mt = 0; mt < 2; mt++)
                #pragma unroll
                for (int nt = 0; nt < 8; nt++)
                    mma_tf32(acc[mt][nt], af[mt], bf[nt]);
        }
        __syncthreads();
    }

    // exchange acc via smem (Cs aliases As/Bs; guarded by syncthreads)
    #pragma unroll
    for (int mt = 0; mt < 2; mt++) {
        int row0 = wm*32 + mt*16 + g;
        #pragma unroll
        for (int nt = 0; nt < 8; nt++) {
            int col0 = wn*64 + nt*8 + t4*2;
            Cs[row0*132 + col0]       = acc[mt][nt][0];
            Cs[row0*132 + col0 + 1]   = acc[mt][nt][1];
            Cs[(row0+8)*132 + col0]   = acc[mt][nt][2];
            Cs[(row0+8)*132 + col0+1] = acc[mt][nt][3];
        }
    }
    __syncthreads();

    // gates: 64 b x 32 hh = 2048 cells, 16 per thread
    #pragma unroll
    for (int i = 0; i < 16; i++) {
        int cell = i*128 + tid;
        int b_l = cell >> 5, hh_l = cell & 31;
        int b = bm + b_l, hh = hh0 + hh_l;
        const float* xrow = Xg + (size_t)(b*L_ + t)*(4*H_);
        float gi = Cs[b_l*132 + 0*32 + hh_l] + xrow[hh]        + bhh[hh];
        float gf = Cs[b_l*132 + 1*32 + hh_l] + xrow[H_+hh]     + bhh[H_+hh];
        float gc = Cs[b_l*132 + 2*32 + hh_l] + xrow[2*H_+hh]   + bhh[2*H_+hh];
        float go = Cs[b_l*132 + 3*32 + hh_l] + xrow[3*H_+hh]   + bhh[3*H_+hh];
        size_t idx = (size_t)b*H_ + hh;
        if (t < lengths[b]) {
            float cn = sigmoidf_(gf)*cst[idx] + sigmoidf_(gi)*tanhf(gc);
            cst[idx] = cn;
            hout[idx] = sigmoidf_(go)*tanhf(cn);
        } else {
            hout[idx] = hin[idx];
        }
    }
}

// ---------------- fused decoder RNN + attention ----------------
__global__ void __launch_bounds__(256)
dec_attn_k(const float* __restrict__ Q,
           const float* __restrict__ WihT,
           const float* __restrict__ WhhT,
           const float* __restrict__ bih, const float* __restrict__ bhh,
           const float* __restrict__ Vt,
           const int* __restrict__ lengths,
           float* __restrict__ R)
{
    int b = blockIdx.x, tid = threadIdx.x;
    __shared__ float shh[H_], sQ[H_], sh[H_];
    __shared__ float sV[L_][H_];
    __shared__ float sHins[STEPS_][H_];
    __shared__ float satt[STEPS_][L_];

    shh[tid] = Q[(size_t)b*H_ + tid];
    for (int i = tid; i < L_*H_; i += 256) sV[i>>8][i&255] = Vt[(size_t)b*L_*H_ + i];
    __syncthreads();

    float acc = bih[tid];
    #pragma unroll 8
    for (int k = 0; k < H_; k++) acc = fmaf(shh[k], WihT[(size_t)k*H_ + tid], acc);
    sQ[tid] = acc;
    sh[tid] = 0.f;
    __syncthreads();

    for (int s = 0; s < STEPS_; s++) {
        float v = sQ[tid] + bhh[tid];
        #pragma unroll 8
        for (int k = 0; k < H_; k++) v = fmaf(sh[k], WhhT[(size_t)k*H_ + tid], v);
        v = fmaxf(v, 0.f);
        __syncthreads();
        sh[tid] = v;
        sHins[s][tid] = v;
        __syncthreads();
    }

    int warp = tid >> 5, lane = tid & 31;
    for (int pid = warp; pid < STEPS_*L_; pid += 8) {
        int s = pid >> 4, l = pid & 15;
        float a = 0.f;
        #pragma unroll
        for (int q = 0; q < H_/32; q++) a = fmaf(sHins[s][lane+32*q], sV[l][lane+32*q], a);
        a = warp_sum(a);
        if (lane == 0) satt[s][l] = a;
    }
    __syncthreads();
    if (tid < STEPS_) {
        int len = lengths[b];
        float m = -3.4e38f;
        for (int l = 0; l < len; l++) m = fmaxf(m, satt[tid][l]);
        float s = 0.f;
        for (int l = 0; l < len; l++) { float e = expf(satt[tid][l]-m); satt[tid][l]=e; s+=e; }
        float inv = 1.f/s;
        for (int l = 0; l < L_; l++) satt[tid][l] = (l < len) ? satt[tid][l]*inv : 0.f;
    }
    __syncthreads();
    for (int s = 0; s < STEPS_; s++) {
        float a2 = 0.f;
        #pragma unroll
        for (int l = 0; l < L_; l++) a2 = fmaf(satt[s][l], sV[l][tid], a2);
        R[((size_t)b*STEPS_ + s)*H_ + tid] = a2;
    }
}

// ---------------- small kernels ----------------
__global__ void build_c_k(const float* __restrict__ vocab, const float* __restrict__ de,
                          float* __restrict__ Cc) {
    int i = blockIdx.x*256 + threadIdx.x;
    if (i < (V_+1)*H_) Cc[i] = (i < V_*H_) ? vocab[i] : de[i - (size_t)V_*H_];
}

__global__ void transpose_wn_k(const float* __restrict__ W, float* __restrict__ WT) {
    __shared__ float t[32][33];
    int rb = blockIdx.y*32, cb = blockIdx.x*32;
    int x = threadIdx.x, y = threadIdx.y;
    for (int j = y; j < 32; j += 8) t[j][x] = W[(size_t)(rb+j)*H_ + cb + x];
    __syncthreads();
    for (int j = y; j < 32; j += 8) WT[(size_t)(cb+j)*H_ + rb + x] = t[x][j];
}

__global__ void vocab_t_k(const float* __restrict__ vocab, float* __restrict__ vt) {
    __shared__ float t[32][33];
    int vb = blockIdx.x*32, hb = blockIdx.y*32;
    int x = threadIdx.x, y = threadIdx.y;
    for (int j = y; j < 32; j += 8) {
        int v = vb + j;
        t[j][x] = (v < V_) ? vocab[(size_t)v*H_ + hb + x] : 0.f;
    }
    __syncthreads();
    for (int j = y; j < 32; j += 8) {
        int v = vb + x;
        if (v < LDLOG_) vt[(size_t)(hb+j)*LDLOG_ + v] = t[x][j];
    }
}

__global__ void zero_k(float* __restrict__ p, int n) {
    int i = blockIdx.x*256 + threadIdx.x;
    if (i < n) p[i] = 0.f;
}

// 3-pass softmax with single exp pass: p1 max, p2 write exp(x-M)+sum, p3 scale.
__global__ void row_softmax_w_k(float* __restrict__ Lg) {
    int r = blockIdx.x;
    float* row = Lg + (size_t)r*LDLOG_;
    __shared__ float red[256];
    float m = -3.4e38f;
    for (int j = threadIdx.x; j < V_+1; j += 256) m = fmaxf(m, row[j]);
    red[threadIdx.x] = m; __syncthreads();
    for (int o = 128; o > 0; o >>= 1) {
        if (threadIdx.x < o) red[threadIdx.x] = fmaxf(red[threadIdx.x], red[threadIdx.x+o]);
        __syncthreads();
    }
    float M = red[0]; __syncthreads();
    float s = 0.f;
    for (int j = threadIdx.x; j < V_+1; j += 256) {
        float e = expf(row[j] - M);
        row[j] = e;
        s += e;
    }
    red[threadIdx.x] = s; __syncthreads();
    for (int o = 128; o > 0; o >>= 1) {
        if (threadIdx.x < o) red[threadIdx.x] += red[threadIdx.x+o];
        __syncthreads();
    }
    float inv = 1.f/red[0];
    for (int j = threadIdx.x; j < V_+1; j += 256)
        row[j] *= inv;
}

__global__ void vtag_eps_k(const float* __restrict__ words, const float* __restrict__ Lg,
                           float* __restrict__ Vt) {
    int i = blockIdx.x*256 + threadIdx.x;
    int r = i >> 8;
    float w = Lg[(size_t)r*LDLOG_ + V_];
    Vt[i] += w * words[i];
}

__global__ void __launch_bounds__(128)
prop_all_k(const float* __restrict__ R, const float* __restrict__ pe,
           float* __restrict__ ps4) {
    int b = blockIdx.x, s = blockIdx.y;
    int p = threadIdx.x >> 5, lane = threadIdx.x & 31;
    const float* instr = R + ((size_t)b*STEPS_ + s)*H_;
    float acc = 0.f;
    for (int h = lane; h < H_; h += 32) acc = fmaf(instr[h], pe[p*H_ + h], acc);
    acc = warp_sum(acc);
    __shared__ float s4[P_];
    if (lane == 0) s4[p] = acc;
    __syncthreads();
    if (threadIdx.x == 0) {
        float m = fmaxf(fmaxf(s4[0], s4[1]), fmaxf(s4[2], s4[3]));
        float e0 = expf(s4[0]-m), e1 = expf(s4[1]-m), e2 = expf(s4[2]-m), e3 = expf(s4[3]-m);
        float inv = 1.f/(e0+e1+e2+e3);
        float* o = ps4 + ((size_t)b*STEPS_ + s)*P_;
        o[0]=e0*inv; o[1]=e1*inv; o[2]=e2*inv; o[3]=e3*inv;
    }
}

#define NODE_BLKS (N_/8)
#define EDGE_BLKS (E_/8)
__global__ void __launch_bounds__(256)
scores_k(const float* __restrict__ Tr, const float* __restrict__ Et,
         const float* __restrict__ R, const float* __restrict__ ps4,
         const float* __restrict__ Wst, const float* __restrict__ Wrel,
         const int* __restrict__ ng, const int* __restrict__ eg,
         float* __restrict__ ns4, float* __restrict__ es4) {
    int bid = blockIdx.x;
    int warp = threadIdx.x >> 5, lane = threadIdx.x & 31;
    if (bid < NODE_BLKS) {
        int n = bid*8 + warp;
        int g = ng[n];
        const float* T = Tr + (size_t)n*3*H_;
        float t0[8], t1[8], t2[8], ws[8];
        #pragma unroll
        for (int q = 0; q < 8; q++) {
            int h = lane + 32*q;
            t0[q] = T[h]; t1[q] = T[H_+h]; t2[q] = T[2*H_+h]; ws[q] = Wst[h];
        }
        float out[STEPS_];
        #pragma unroll
        for (int s = 0; s < STEPS_; s++) {
            const float* pp = ps4 + ((size_t)g*STEPS_ + s)*P_;
            float p0 = pp[0], p1 = pp[1], p2 = pp[2];
            const float* instr = R + ((size_t)g*STEPS_ + s)*H_;
            float acc = 0.f;
            #pragma unroll
            for (int q = 0; q < 8; q++) {
                int h = lane + 32*q;
                float tv = p0*t0[q] + p1*t1[q] + p2*t2[q];
                float x = instr[h]*tv;
                float e = (x > 0.f) ? x : expm1f(x);
                acc = fmaf(e, ws[q], acc);
            }
            out[s] = warp_sum(acc);
        }
        if (lane == 0)
            *reinterpret_cast<float4*>(ns4 + (size_t)n*4) =
                make_float4(out[0], out[1], out[2], out[3]);
    } else {
        int e = (bid - NODE_BLKS)*8 + warp;
        int g = eg[e];
        const float* et = Et + (size_t)e*H_;
        float ev[8], wr[8];
        #pragma unroll
        for (int q = 0; q < 8; q++) {
            int h = lane + 32*q;
            ev[q] = et[h]; wr[q] = Wrel[h];
        }
        float out[STEPS_];
        #pragma unroll
        for (int s = 0; s < STEPS_; s++) {
            const float* instr = R + ((size_t)g*STEPS_ + s)*H_;
            float acc = 0.f;
            #pragma unroll
            for (int q = 0; q < 8; q++) {
                int h = lane + 32*q;
                float x = instr[h]*ev[q];
                float el = (x > 0.f) ? x : expm1f(x);
                acc = fmaf(el, wr[q], acc);
            }
            out[s] = warp_sum(acc);
        }
        if (lane == 0)
            *reinterpret_cast<float4*>(es4 + (size_t)e*4) =
                make_float4(out[0], out[1], out[2], out[3]);
    }
}

__global__ void __launch_bounds__(256)
graph_loop_k(const float* __restrict__ ns4, const float* __restrict__ es4,
             const float* __restrict__ ps4,
             const int* __restrict__ esrc, const int* __restrict__ edst,
             float* __restrict__ dist_out) {
    int g = blockIdx.x, tid = threadIdx.x;
    __shared__ float dist[NPG_], agg[NPG_], red[256];
    __shared__ int lsrc[EPG_], ldst[EPG_];
    __shared__ float4 ns[NPG_];

    int nbase = g*NPG_, ebase = g*EPG_;
    for (int e = tid; e < EPG_; e += 256) {
        lsrc[e] = esrc[ebase + e] - nbase;
        ldst[e] = edst[ebase + e] - nbase;
    }
    if (tid < NPG_) {
        dist[tid] = 1.f/(float)NPG_;
        ns[tid] = *reinterpret_cast<const float4*>(ns4 + (size_t)(nbase + tid)*4);
    }
    __syncthreads();

    for (int s = 0; s < STEPS_; s++) {
        if (tid < NPG_) agg[tid] = 0.f;
        __syncthreads();
        for (int e = tid; e < EPG_; e += 256) {
            float sc = es4[(size_t)(ebase + e)*4 + s];
            atomicAdd(&agg[ldst[e]], dist[lsrc[e]]*sc);
        }
        __syncthreads();

        float nsv = (tid < NPG_) ? ((const float*)&ns[tid])[s] : -3.4e38f;
        float agv = (tid < NPG_) ? agg[tid] : -3.4e38f;
        red[tid] = nsv; __syncthreads();
        for (int o = 128; o > 0; o >>= 1) { if (tid < o) red[tid] = fmaxf(red[tid], red[tid+o]); __syncthreads(); }
        float m1 = red[0]; __syncthreads();
        red[tid] = agv; __syncthreads();
        for (int o = 128; o > 0; o >>= 1) { if (tid < o) red[tid] = fmaxf(red[tid], red[tid+o]); __syncthreads(); }
        float m2 = red[0]; __syncthreads();
        float e1 = (tid < NPG_) ? expf(nsv - m1) : 0.f;
        float e2 = (tid < NPG_) ? expf(agv - m2) : 0.f;
        red[tid] = e1; __syncthreads();
        for (int o = 128; o > 0; o >>= 1) { if (tid < o) red[tid] += red[tid+o]; __syncthreads(); }
        float s1 = red[0]; __syncthreads();
        red[tid] = e2; __syncthreads();
        for (int o = 128; o > 0; o >>= 1) { if (tid < o) red[tid] += red[tid+o]; __syncthreads(); }
        float s2 = red[0]; __syncthreads();
        if (tid < NPG_) {
            float r = ps4[((size_t)g*STEPS_ + s)*P_ + 3];
            dist[tid] = r*(e2/s2) + (1.f - r)*(e1/s1);
        }
        __syncthreads();
    }
    if (tid < NPG_) dist_out[nbase + tid] = dist[tid];
}

__global__ void final_agg_qa_k(const float* __restrict__ na, const float* __restrict__ ps4,
                               const float* __restrict__ dist, const float* __restrict__ Q,
                               float* __restrict__ QA) {
    int g = blockIdx.x, h = threadIdx.x;
    const float* pp = ps4 + ((size_t)g*STEPS_ + (STEPS_-1))*P_;
    float p0 = pp[0], p1 = pp[1], p2 = pp[2];
    float acc = 0.f;
    for (int i = 0; i < NPG_; i++) {
        size_t n = (size_t)g*NPG_ + i;
        const float* a = na + n*3*H_;
        float nf = p0*a[h] + p1*a[H_+h] + p2*a[2*H_+h];
        acc = fmaf(dist[n], nf, acc);
    }
    QA[(size_t)g*2*H_ + h]      = Q[(size_t)g*H_ + h];
    QA[(size_t)g*2*H_ + H_ + h] = acc;
}

// ---------------- launchers ----------------
static inline void tc_gemm(const float* A, int lda, const float* Bm, int ldb,
                           float* C, int ldc, int M, int N, int K,
                           const float* bias, int splitk = 1) {
    dim3 g((N + GB_N - 1)/GB_N, (M + GB_M - 1)/GB_M, splitk);
    mma_gemm_k<<<g, 128, G_SMEM_BYTES>>>(A, lda, Bm, ldb, C, ldc, M, N, K, bias, splitk);
}

extern "C" void kernel_launch(void* const* d_in, const int* in_sizes, int n_in,
                              void* d_out, int out_size) {
    const float* questions     = (const float*)d_in[0];
    const float* node_attrs    = (const float*)d_in[1];
    const float* edge_attrs    = (const float*)d_in[2];
    const float* vocab         = (const float*)d_in[3];
    const float* default_embed = (const float*)d_in[4];
    const float* W_norm        = (const float*)d_in[5];
    const float* lstm_Wih      = (const float*)d_in[6];
    const float* lstm_Whh      = (const float*)d_in[7];
    const float* lstm_bih      = (const float*)d_in[8];
    const float* lstm_bhh      = (const float*)d_in[9];
    const float* rnn_Wih       = (const float*)d_in[10];
    const float* rnn_Whh       = (const float*)d_in[11];
    const float* rnn_bih       = (const float*)d_in[12];
    const float* rnn_bhh       = (const float*)d_in[13];
    const float* prop_embeds   = (const float*)d_in[14];
    const float* Ws_property   = (const float*)d_in[15];
    const float* W_state       = (const float*)d_in[16];
    const float* W_relation    = (const float*)d_in[17];
    const float* lin_W         = (const float*)d_in[18];
    const float* lin_b         = (const float*)d_in[19];
    const int*   lengths       = (const int*)d_in[20];
    const int*   node_graph    = (const int*)d_in[21];
    const int*   edge_graph    = (const int*)d_in[22];
    const int*   edge_src      = (const int*)d_in[23];
    const int*   edge_dst      = (const int*)d_in[24];
    float* out = (float*)d_out;

    cudaFuncSetAttribute(mma_gemm_k, cudaFuncAttributeMaxDynamicSharedMemorySize, G_SMEM_BYTES);
    cudaFuncSetAttribute(lstm_mma_k, cudaFuncAttributeMaxDynamicSharedMemorySize, L_SMEM_BYTES);

    float* S = nullptr;
    cudaGetSymbolAddress((void**)&S, g_scratch);
    float* Cc   = S + OFF_C;
    float* XW   = S + OFF_XW;
    float* LG   = S + OFF_LOG;
    float* VT   = S + OFF_VT;
    float* XG   = S + OFF_XG;
    float* H0   = S + OFF_H;
    float* Cst  = S + OFF_CS;
    float* H1   = S + OFF_H2;
    float* Rr   = S + OFF_R;
    float* PS4  = S + OFF_PS;
    float* TR   = S + OFF_TR;
    float* ET   = S + OFF_ET;
    float* NS4  = S + OFF_NS4;
    float* ES4  = S + OFF_ES4;
    float* DIST = S + OFF_DIST;
    float* QA   = S + OFF_QA;
    float* WNT  = S + OFF_WNT;
    float* VOCT = S + OFF_VOCT;
    float* WIHT = S + OFF_WIHT;
    float* WHHT = S + OFF_WHHT;

    // 0. one-time layout prep
    build_c_k<<<((V_+1)*H_ + 255)/256, 256>>>(vocab, default_embed, Cc);
    transpose_wn_k<<<dim3(8,8), dim3(32,8)>>>(W_norm, WNT);
    transpose_wn_k<<<dim3(8,8), dim3(32,8)>>>(rnn_Wih, WIHT);
    transpose_wn_k<<<dim3(8,8), dim3(32,8)>>>(rnn_Whh, WHHT);
    vocab_t_k<<<dim3((LDLOG_+31)/32, H_/32), dim3(32,8)>>>(vocab, VOCT);

    // 1. vocab tagging
    tc_gemm(questions, H_, WNT, H_, XW, H_, BL_, H_, H_, nullptr);
    tc_gemm(XW, H_, Cc, H_, LG, LDLOG_, BL_, V_+1, H_, nullptr);
    row_softmax_w_k<<<BL_, 256>>>(LG);
    zero_k<<<(BL_*H_ + 255)/256, 256>>>(VT, BL_*H_);
    tc_gemm(LG, LDLOG_, VOCT, LDLOG_, VT, H_, BL_, H_, V_, nullptr, 4);
    vtag_eps_k<<<BL_*H_/256, 256>>>(questions, LG, VT);

    // 2. LSTM encoder (tensor-core fused step)
    tc_gemm(VT, H_, lstm_Wih, H_, XG, 4*H_, BL_, 4*H_, H_, lstm_bih);
    zero_k<<<(2*B_*H_ + 255)/256, 256>>>(H0, 2*B_*H_);
    for (int t = 0; t < L_; t++) {
        const float* hin = (t & 1) ? H1 : H0;
        float* hout      = (t & 1) ? H0 : H1;
        lstm_mma_k<<<dim3(H_/32, B_/64), 128, L_SMEM_BYTES>>>(hin, hout, Cst, XG,
                                                              lstm_Whh, lstm_bhh, lengths, t);
    }

    // 3. fused decoder + attention
    dec_attn_k<<<B_, 256>>>(H0, WIHT, WHHT, rnn_bih, rnn_bhh, VT, lengths, Rr);

    // 4. loop-invariant graph transforms
    for (int p = 0; p < 3; p++)
        tc_gemm(node_attrs + p*H_, 3*H_, Ws_property + (size_t)p*H_*H_, H_,
                TR + p*H_, 3*H_, N_, H_, H_, nullptr);
    tc_gemm(edge_attrs, H_, Ws_property + (size_t)3*H_*H_, H_, ET, H_, E_, H_, H_, nullptr);

    // 5. reasoning
    prop_all_k<<<dim3(B_, STEPS_), 128>>>(Rr, prop_embeds, PS4);
    scores_k<<<NODE_BLKS + EDGE_BLKS, 256>>>(TR, ET, Rr, PS4, W_state, W_relation,
                                             node_graph, edge_graph, NS4, ES4);
    graph_loop_k<<<B_, 256>>>(NS4, ES4, PS4, edge_src, edge_dst, DIST);

    // 6. final aggregation + output projection
    final_agg_qa_k<<<B_, 256>>>(node_attrs, PS4, DIST, H0, QA);
    zero_k<<<(B_*OUT_ + 255)/256, 256>>>(out, B_*OUT_);
    tc_gemm(QA, 2*H_, lin_W, 2*H_, out, OUT_, B_, OUT_, 2*H_, lin_b, 4);
}